// round 1
// baseline (speedup 1.0000x reference)
#include <cuda_runtime.h>

#define NB 4
#define SEQ 4096
#define DIM 1024
#define NH 16
#define HDIM 64
#define WINS 512
#define NWIN 8
#define NGT 128

// ---------------- scratch (static device globals; no allocation) ----------------
__device__ float g_xpos[NB * SEQ * DIM];   // x + pos_emb
__device__ float g_local[NB * SEQ * DIM];  // local attention out
__device__ float g_glob[NB * SEQ * DIM];   // global attention out
__device__ float g_mixed[NB * SEQ * DIM];  // gated mix
__device__ float g_gt[NB * NGT * DIM];     // [comp ; global_memory] per batch

// ---------------- kernel 1: x + pos_emb ----------------
__global__ __launch_bounds__(256) void add_pos_kernel(const float* __restrict__ x,
                                                      const float* __restrict__ pe) {
    int i = blockIdx.x * 256 + threadIdx.x;           // over 4,194,304 float4s
    float4 a = ((const float4*)x)[i];
    float4 p = ((const float4*)pe)[i & 1048575];      // pos repeats every S*D/4
    float4 r;
    r.x = a.x + p.x; r.y = a.y + p.y; r.z = a.z + p.z; r.w = a.w + p.w;
    ((float4*)g_xpos)[i] = r;
}

// ---------------- kernel: fill global_memory half of gt ----------------
__global__ __launch_bounds__(256) void gt_fill_kernel(const float* __restrict__ gm) {
    int i = blockIdx.x * 256 + threadIdx.x;           // 65536 float4s total
    float4 v = ((const float4*)gm)[i & 16383];        // 64*1024/4 per batch
    ((float4*)g_gt)[(i >> 14) * 32768 + 16384 + (i & 16383)] = v;
}

// ---------------- flash attention core (64 q-rows per block, 256 threads) ----------------
// smem: Qt[64][68] (transposed, pre-scaled), Kt[64][68] (transposed),
//       Vs[64][68] (row-major), Pt[64][68] (P transposed)
__device__ __forceinline__ void flash_core(const float* __restrict__ qb,
                                           const float* __restrict__ kb,
                                           float* __restrict__ obp, int nkt) {
    extern __shared__ float sm[];
    float* Qt = sm;
    float* Kt = sm + 4352;
    float* Vs = sm + 8704;
    float* Pt = sm + 13056;
    const int tid = threadIdx.x, tx = tid & 15, ty = tid >> 4;
    const float scale = 0.125f;  // 1/sqrt(64)

    // load Q transposed, pre-scaled
#pragma unroll
    for (int it = 0; it < 4; ++it) {
        int f = tid + it * 256;
        int row = f >> 4, c4 = (f & 15) << 2;
        float4 v = *(const float4*)(qb + row * DIM + c4);
        Qt[(c4 + 0) * 68 + row] = v.x * scale;
        Qt[(c4 + 1) * 68 + row] = v.y * scale;
        Qt[(c4 + 2) * 68 + row] = v.z * scale;
        Qt[(c4 + 3) * 68 + row] = v.w * scale;
    }
    float m[4], l[4], acc[4][4];
#pragma unroll
    for (int i = 0; i < 4; i++) {
        m[i] = -1e30f; l[i] = 0.f;
#pragma unroll
        for (int j = 0; j < 4; j++) acc[i][j] = 0.f;
    }

    for (int kt = 0; kt < nkt; ++kt) {
        __syncthreads();
        // K (=V) tile: transposed into Kt, row-major into Vs (same data, q=k=v)
#pragma unroll
        for (int it = 0; it < 4; ++it) {
            int f = tid + it * 256;
            int row = f >> 4, c4 = (f & 15) << 2;
            float4 v = *(const float4*)(kb + (kt * 64 + row) * DIM + c4);
            Kt[(c4 + 0) * 68 + row] = v.x;
            Kt[(c4 + 1) * 68 + row] = v.y;
            Kt[(c4 + 2) * 68 + row] = v.z;
            Kt[(c4 + 3) * 68 + row] = v.w;
            *(float4*)(Vs + row * 68 + c4) = v;
        }
        __syncthreads();

        // S = (Q*scale) K^T, 4x4 microtile per thread
        float s[4][4];
#pragma unroll
        for (int i = 0; i < 4; i++)
#pragma unroll
            for (int j = 0; j < 4; j++) s[i][j] = 0.f;
#pragma unroll 8
        for (int d = 0; d < 64; ++d) {
            float4 qv = *(const float4*)(Qt + d * 68 + (ty << 2));
            float4 kv = *(const float4*)(Kt + d * 68 + (tx << 2));
            float qa[4] = {qv.x, qv.y, qv.z, qv.w};
            float ka[4] = {kv.x, kv.y, kv.z, kv.w};
#pragma unroll
            for (int i = 0; i < 4; i++)
#pragma unroll
                for (int j = 0; j < 4; j++) s[i][j] += qa[i] * ka[j];
        }

        // online softmax (row stats replicated across the 16 tx-threads of a row group)
        float rmax[4];
#pragma unroll
        for (int i = 0; i < 4; i++)
            rmax[i] = fmaxf(fmaxf(s[i][0], s[i][1]), fmaxf(s[i][2], s[i][3]));
#pragma unroll
        for (int off = 8; off >= 1; off >>= 1) {
#pragma unroll
            for (int i = 0; i < 4; i++)
                rmax[i] = fmaxf(rmax[i], __shfl_xor_sync(0xffffffffu, rmax[i], off));
        }
        float psum[4];
#pragma unroll
        for (int i = 0; i < 4; i++) {
            float mnew = fmaxf(m[i], rmax[i]);
            float corr = __expf(m[i] - mnew);
            m[i] = mnew;
#pragma unroll
            for (int j = 0; j < 4; j++) s[i][j] = __expf(s[i][j] - mnew);
            psum[i] = s[i][0] + s[i][1] + s[i][2] + s[i][3];
            l[i] *= corr;
#pragma unroll
            for (int j = 0; j < 4; j++) acc[i][j] *= corr;
        }
#pragma unroll
        for (int off = 8; off >= 1; off >>= 1) {
#pragma unroll
            for (int i = 0; i < 4; i++)
                psum[i] += __shfl_xor_sync(0xffffffffu, psum[i], off);
        }
#pragma unroll
        for (int i = 0; i < 4; i++) l[i] += psum[i];

        // P transposed to smem for the PV product
#pragma unroll
        for (int j = 0; j < 4; j++) {
            float4 pv = make_float4(s[0][j], s[1][j], s[2][j], s[3][j]);
            *(float4*)(Pt + ((tx << 2) + j) * 68 + (ty << 2)) = pv;
        }
        __syncthreads();
        // O += P V
#pragma unroll 8
        for (int k2 = 0; k2 < 64; ++k2) {
            float4 pv = *(const float4*)(Pt + k2 * 68 + (ty << 2));
            float4 vv = *(const float4*)(Vs + k2 * 68 + (tx << 2));
            float pa[4] = {pv.x, pv.y, pv.z, pv.w};
            float va[4] = {vv.x, vv.y, vv.z, vv.w};
#pragma unroll
            for (int i = 0; i < 4; i++)
#pragma unroll
                for (int j = 0; j < 4; j++) acc[i][j] += pa[i] * va[j];
        }
    }

#pragma unroll
    for (int i = 0; i < 4; i++) {
        float inv = 1.0f / l[i];
        float4 o = make_float4(acc[i][0] * inv, acc[i][1] * inv,
                               acc[i][2] * inv, acc[i][3] * inv);
        *(float4*)(obp + ((ty << 2) + i) * DIM + (tx << 2)) = o;
    }
}

// local: blocks = B*NWIN*NH*8 (q-tiles of 64 inside a 512 window), 8 k-tiles
__global__ __launch_bounds__(256) void local_attn_kernel() {
    int bx = blockIdx.x;
    int qt = bx & 7;
    int h = (bx >> 3) & 15;
    int w = (bx >> 7) & 7;
    int b = bx >> 10;
    const float* base = g_xpos + (b * SEQ + w * WINS) * DIM + h * HDIM;
    const float* qb = base + (qt * 64) * DIM;
    float* ob = g_local + (b * SEQ + w * WINS + qt * 64) * DIM + h * HDIM;
    flash_core(qb, base, ob, 8);
}

// global: blocks = B*NH*64 (q-tiles of 64 across S), 2 k-tiles over gt (128 tokens)
__global__ __launch_bounds__(256) void global_attn_kernel() {
    int bx = blockIdx.x;
    int qt = bx & 63;
    int h = (bx >> 6) & 15;
    int b = bx >> 10;
    const float* qb = g_xpos + (b * SEQ + qt * 64) * DIM + h * HDIM;
    const float* kb = g_gt + (b * NGT) * DIM + h * HDIM;
    float* ob = g_glob + (b * SEQ + qt * 64) * DIM + h * HDIM;
    flash_core(qb, kb, ob, 2);
}

// ---------------- SIMT fp32 GEMM, 128x128x16 tiles, 256 threads, 8x8 per thread ----
// MODE 0: comp = gather(xpos) @ conv_w^T + conv_b  -> g_gt (rows remapped, M=256,K=4096)
// MODE 1: z = [local|glob] @ gate_w + gate_b; mixed = sig(z)*local+(1-sig)*glob (K=2048)
// MODE 2: out = mixed @ out_w + out_b -> Cext (K=1024)
template <int MODE>
__global__ __launch_bounds__(256) void gemm128(const float* __restrict__ Bw,
                                               const float* __restrict__ bias,
                                               float* __restrict__ Cext) {
    constexpr int K = (MODE == 0) ? 4096 : (MODE == 1 ? 2048 : 1024);
    __shared__ float As[16 * 132];  // As[k][m]
    __shared__ float Bs[16 * 132];  // Bs[k][n]
    const int m0 = blockIdx.y * 128, n0 = blockIdx.x * 128;
    const int tid = threadIdx.x, tx = tid & 15, ty = tid >> 4;
    float acc[8][8];
#pragma unroll
    for (int i = 0; i < 8; i++)
#pragma unroll
        for (int j = 0; j < 8; j++) acc[i][j] = 0.f;

    for (int k0 = 0; k0 < K; k0 += 16) {
        __syncthreads();
        // ---- A tile -> As[k][m] (transposed in smem) ----
#pragma unroll
        for (int it = 0; it < 2; ++it) {
            int f = tid + it * 256;
            int row = f >> 2, c4 = (f & 3) << 2;
            float4 v;
            if (MODE == 0) {
                // virtual A[(b,g), c], c = ktap*1024 + din  ->  xpos[b, 4g+ktap, din]
                int r = m0 + row;
                int c = k0 + c4;
                int ktap = c >> 10, din = c & 1023;
                int b = r >> 6, g = r & 63;
                v = *(const float4*)(g_xpos + ((b << 12) + (g << 2) + ktap) * DIM + din);
            } else if (MODE == 1) {
                int c = k0 + c4;
                const float* src = (c < 1024)
                                       ? (g_local + (m0 + row) * 1024 + c)
                                       : (g_glob + (m0 + row) * 1024 + (c - 1024));
                v = *(const float4*)src;
            } else {
                v = *(const float4*)(g_mixed + (m0 + row) * 1024 + k0 + c4);
            }
            As[(c4 + 0) * 132 + row] = v.x;
            As[(c4 + 1) * 132 + row] = v.y;
            As[(c4 + 2) * 132 + row] = v.z;
            As[(c4 + 3) * 132 + row] = v.w;
        }
        // ---- B tile -> Bs[k][n] ----
        if (MODE == 0) {
            // conv_w layout [dout][din][ktap]; c = ktap*1024 + din
#pragma unroll
            for (int it = 0; it < 8; ++it) {
                int f = tid + it * 256;
                int n = f >> 4, kk = f & 15;
                int c = k0 + kk;
                int ktap = c >> 10, din = c & 1023;
                Bs[kk * 132 + n] = Bw[(n0 + n) * 4096 + (din << 2) + ktap];
            }
        } else {
#pragma unroll
            for (int it = 0; it < 2; ++it) {
                int f = tid + it * 256;
                int row = f >> 5, c4 = (f & 31) << 2;
                float4 v = *(const float4*)(Bw + (k0 + row) * 1024 + n0 + c4);
                *(float4*)&Bs[row * 132 + c4] = v;
            }
        }
        __syncthreads();
#pragma unroll
        for (int kk = 0; kk < 16; ++kk) {
            float a[8], bb[8];
            *(float4*)(a) = *(const float4*)&As[kk * 132 + ty * 8];
            *(float4*)(a + 4) = *(const float4*)&As[kk * 132 + ty * 8 + 4];
            *(float4*)(bb) = *(const float4*)&Bs[kk * 132 + tx * 8];
            *(float4*)(bb + 4) = *(const float4*)&Bs[kk * 132 + tx * 8 + 4];
#pragma unroll
            for (int i = 0; i < 8; i++)
#pragma unroll
                for (int j = 0; j < 8; j++) acc[i][j] += a[i] * bb[j];
        }
    }
    // ---- epilogue ----
#pragma unroll
    for (int i = 0; i < 8; ++i) {
        int r = m0 + ty * 8 + i;
        int cb0 = n0 + tx * 8;
#pragma unroll
        for (int j = 0; j < 8; ++j) {
            float z = acc[i][j] + bias[cb0 + j];
            if (MODE == 0) {
                int outr = ((r >> 6) << 7) | (r & 63);  // (b,g) -> gt row b*128+g
                g_gt[outr * 1024 + cb0 + j] = z;
            } else if (MODE == 1) {
                float sg = 1.0f / (1.0f + __expf(-z));
                int idx = r * 1024 + cb0 + j;
                g_mixed[idx] = sg * g_local[idx] + (1.0f - sg) * g_glob[idx];
            } else {
                Cext[r * 1024 + cb0 + j] = z;
            }
        }
    }
}

// ---------------- launch ----------------
extern "C" void kernel_launch(void* const* d_in, const int* in_sizes, int n_in,
                              void* d_out, int out_size) {
    const float* x = (const float*)d_in[0];
    const float* pe = (const float*)d_in[1];
    const float* gm = (const float*)d_in[2];
    const float* cw = (const float*)d_in[3];
    const float* cb = (const float*)d_in[4];
    const float* gw = (const float*)d_in[5];
    const float* gb = (const float*)d_in[6];
    const float* ow = (const float*)d_in[7];
    const float* ob = (const float*)d_in[8];
    float* out = (float*)d_out;

    // 68KB dynamic smem for the flash kernels (idempotent; legal during capture)
    cudaFuncSetAttribute((const void*)local_attn_kernel,
                         cudaFuncAttributeMaxDynamicSharedMemorySize, 69632);
    cudaFuncSetAttribute((const void*)global_attn_kernel,
                         cudaFuncAttributeMaxDynamicSharedMemorySize, 69632);

    add_pos_kernel<<<16384, 256>>>(x, pe);
    gemm128<0><<<dim3(8, 2), 256>>>(cw, cb, nullptr);     // conv -> gt[:,0:64,:]
    gt_fill_kernel<<<256, 256>>>(gm);                      // gt[:,64:128,:]
    local_attn_kernel<<<4096, 256, 69632>>>();
    global_attn_kernel<<<4096, 256, 69632>>>();
    gemm128<1><<<dim3(8, 128), 256>>>(gw, gb, nullptr);   // gate + mix
    gemm128<2><<<dim3(8, 128), 256>>>(ow, ob, out);       // output projection
}

// round 2
// speedup vs baseline: 1.0825x; 1.0825x over previous
#include <cuda_runtime.h>
#include <cstdint>

#define NB 4
#define SEQ 4096
#define DIM 1024
#define NH 16
#define HDIM 64
#define WINS 512
#define NWIN 8
#define NGT 128

// ---------------- scratch (static device globals; no allocation) ----------------
__device__ float g_xpos[NB * SEQ * DIM];   // x + pos_emb
__device__ float g_local[NB * SEQ * DIM];  // local attention out
__device__ float g_glob[NB * SEQ * DIM];   // global attention out
__device__ float g_mixed[NB * SEQ * DIM];  // gated mix
__device__ float g_gt[NB * NGT * DIM];     // [comp ; global_memory] per batch

// ---------------- helpers ----------------
__device__ __forceinline__ uint32_t f2tf32(float x) {
    uint32_t r;
    asm("cvt.rna.tf32.f32 %0, %1;" : "=r"(r) : "f"(x));
    return r;
}

__device__ __forceinline__ void mma_tf32(float* c, uint32_t a0, uint32_t a1,
                                         uint32_t a2, uint32_t a3,
                                         uint32_t b0, uint32_t b1) {
    asm volatile(
        "mma.sync.aligned.m16n8k8.row.col.f32.tf32.tf32.f32 "
        "{%0,%1,%2,%3}, {%4,%5,%6,%7}, {%8,%9}, {%0,%1,%2,%3};"
        : "+f"(c[0]), "+f"(c[1]), "+f"(c[2]), "+f"(c[3])
        : "r"(a0), "r"(a1), "r"(a2), "r"(a3), "r"(b0), "r"(b1));
}

// ---------------- kernel 1: x + pos_emb ----------------
__global__ __launch_bounds__(256) void add_pos_kernel(const float* __restrict__ x,
                                                      const float* __restrict__ pe) {
    int i = blockIdx.x * 256 + threadIdx.x;           // over 4,194,304 float4s
    float4 a = ((const float4*)x)[i];
    float4 p = ((const float4*)pe)[i & 1048575];      // pos repeats every S*D/4
    float4 r;
    r.x = a.x + p.x; r.y = a.y + p.y; r.z = a.z + p.z; r.w = a.w + p.w;
    ((float4*)g_xpos)[i] = r;
}

// ---------------- kernel: fill global_memory half of gt ----------------
__global__ __launch_bounds__(256) void gt_fill_kernel(const float* __restrict__ gm) {
    int i = blockIdx.x * 256 + threadIdx.x;           // 65536 float4s total
    float4 v = ((const float4*)gm)[i & 16383];        // 64*1024/4 per batch
    ((float4*)g_gt)[(i >> 14) * 32768 + 16384 + (i & 16383)] = v;
}

// ---------------- flash attention core (64 q-rows per block, 256 threads) ----------------
__device__ __forceinline__ void flash_core(const float* __restrict__ qb,
                                           const float* __restrict__ kb,
                                           float* __restrict__ obp, int nkt) {
    extern __shared__ float sm[];
    float* Qt = sm;
    float* Kt = sm + 4352;
    float* Vs = sm + 8704;
    float* Pt = sm + 13056;
    const int tid = threadIdx.x, tx = tid & 15, ty = tid >> 4;
    const float scale = 0.125f;  // 1/sqrt(64)

    // load Q transposed, pre-scaled
#pragma unroll
    for (int it = 0; it < 4; ++it) {
        int f = tid + it * 256;
        int row = f >> 4, c4 = (f & 15) << 2;
        float4 v = *(const float4*)(qb + row * DIM + c4);
        Qt[(c4 + 0) * 68 + row] = v.x * scale;
        Qt[(c4 + 1) * 68 + row] = v.y * scale;
        Qt[(c4 + 2) * 68 + row] = v.z * scale;
        Qt[(c4 + 3) * 68 + row] = v.w * scale;
    }
    float m[4], l[4], acc[4][4];
#pragma unroll
    for (int i = 0; i < 4; i++) {
        m[i] = -1e30f; l[i] = 0.f;
#pragma unroll
        for (int j = 0; j < 4; j++) acc[i][j] = 0.f;
    }

    for (int kt = 0; kt < nkt; ++kt) {
        __syncthreads();
#pragma unroll
        for (int it = 0; it < 4; ++it) {
            int f = tid + it * 256;
            int row = f >> 4, c4 = (f & 15) << 2;
            float4 v = *(const float4*)(kb + (kt * 64 + row) * DIM + c4);
            Kt[(c4 + 0) * 68 + row] = v.x;
            Kt[(c4 + 1) * 68 + row] = v.y;
            Kt[(c4 + 2) * 68 + row] = v.z;
            Kt[(c4 + 3) * 68 + row] = v.w;
            *(float4*)(Vs + row * 68 + c4) = v;
        }
        __syncthreads();

        float s[4][4];
#pragma unroll
        for (int i = 0; i < 4; i++)
#pragma unroll
            for (int j = 0; j < 4; j++) s[i][j] = 0.f;
#pragma unroll 8
        for (int d = 0; d < 64; ++d) {
            float4 qv = *(const float4*)(Qt + d * 68 + (ty << 2));
            float4 kv = *(const float4*)(Kt + d * 68 + (tx << 2));
            float qa[4] = {qv.x, qv.y, qv.z, qv.w};
            float ka[4] = {kv.x, kv.y, kv.z, kv.w};
#pragma unroll
            for (int i = 0; i < 4; i++)
#pragma unroll
                for (int j = 0; j < 4; j++) s[i][j] += qa[i] * ka[j];
        }

        float rmax[4];
#pragma unroll
        for (int i = 0; i < 4; i++)
            rmax[i] = fmaxf(fmaxf(s[i][0], s[i][1]), fmaxf(s[i][2], s[i][3]));
#pragma unroll
        for (int off = 8; off >= 1; off >>= 1) {
#pragma unroll
            for (int i = 0; i < 4; i++)
                rmax[i] = fmaxf(rmax[i], __shfl_xor_sync(0xffffffffu, rmax[i], off));
        }
        float psum[4];
#pragma unroll
        for (int i = 0; i < 4; i++) {
            float mnew = fmaxf(m[i], rmax[i]);
            float corr = __expf(m[i] - mnew);
            m[i] = mnew;
#pragma unroll
            for (int j = 0; j < 4; j++) s[i][j] = __expf(s[i][j] - mnew);
            psum[i] = s[i][0] + s[i][1] + s[i][2] + s[i][3];
            l[i] *= corr;
#pragma unroll
            for (int j = 0; j < 4; j++) acc[i][j] *= corr;
        }
#pragma unroll
        for (int off = 8; off >= 1; off >>= 1) {
#pragma unroll
            for (int i = 0; i < 4; i++)
                psum[i] += __shfl_xor_sync(0xffffffffu, psum[i], off);
        }
#pragma unroll
        for (int i = 0; i < 4; i++) l[i] += psum[i];

#pragma unroll
        for (int j = 0; j < 4; j++) {
            float4 pv = make_float4(s[0][j], s[1][j], s[2][j], s[3][j]);
            *(float4*)(Pt + ((tx << 2) + j) * 68 + (ty << 2)) = pv;
        }
        __syncthreads();
#pragma unroll 8
        for (int k2 = 0; k2 < 64; ++k2) {
            float4 pv = *(const float4*)(Pt + k2 * 68 + (ty << 2));
            float4 vv = *(const float4*)(Vs + k2 * 68 + (tx << 2));
            float pa[4] = {pv.x, pv.y, pv.z, pv.w};
            float va[4] = {vv.x, vv.y, vv.z, vv.w};
#pragma unroll
            for (int i = 0; i < 4; i++)
#pragma unroll
                for (int j = 0; j < 4; j++) acc[i][j] += pa[i] * va[j];
        }
    }

#pragma unroll
    for (int i = 0; i < 4; i++) {
        float inv = 1.0f / l[i];
        float4 o = make_float4(acc[i][0] * inv, acc[i][1] * inv,
                               acc[i][2] * inv, acc[i][3] * inv);
        *(float4*)(obp + ((ty << 2) + i) * DIM + (tx << 2)) = o;
    }
}

__global__ __launch_bounds__(256) void local_attn_kernel() {
    int bx = blockIdx.x;
    int qt = bx & 7;
    int h = (bx >> 3) & 15;
    int w = (bx >> 7) & 7;
    int b = bx >> 10;
    const float* base = g_xpos + (b * SEQ + w * WINS) * DIM + h * HDIM;
    const float* qb = base + (qt * 64) * DIM;
    float* ob = g_local + (b * SEQ + w * WINS + qt * 64) * DIM + h * HDIM;
    flash_core(qb, base, ob, 8);
}

__global__ __launch_bounds__(256) void global_attn_kernel() {
    int bx = blockIdx.x;
    int qt = bx & 63;
    int h = (bx >> 6) & 15;
    int b = bx >> 10;
    const float* qb = g_xpos + (b * SEQ + qt * 64) * DIM + h * HDIM;
    const float* kb = g_gt + (b * NGT) * DIM + h * HDIM;
    float* ob = g_glob + (b * SEQ + qt * 64) * DIM + h * HDIM;
    flash_core(qb, kb, ob, 2);
}

// ---------------- TF32 tensor-core GEMM, 128x128 block tile, KT=32 ----------------
// 256 threads = 8 warps, 4x2 warp grid, warp tile 32x64, m16n8k8 tf32 mma.
// MODE 0: comp = gather(xpos) @ conv_w^T + conv_b  -> g_gt (rows remapped, M=256,K=4096)
// MODE 1: z = [local|glob] @ gate_w + gate_b; mixed = sig(z)*local+(1-sig)*glob (K=2048)
// MODE 2: out = mixed @ out_w + out_b -> Cext (K=1024)
#define AS_STRIDE 36
#define BS_STRIDE 136
template <int MODE>
__global__ __launch_bounds__(256) void gemm_tf32(const float* __restrict__ Bw,
                                                 const float* __restrict__ bias,
                                                 float* __restrict__ Cext) {
    constexpr int K = (MODE == 0) ? 4096 : (MODE == 1 ? 2048 : 1024);
    __shared__ float As[128 * AS_STRIDE];  // [m][k], stride 36 -> conflict-free frags
    __shared__ float Bs[32 * BS_STRIDE];   // [k][n], stride 136 -> conflict-free frags
    const int m0 = blockIdx.y * 128, n0 = blockIdx.x * 128;
    const int tid = threadIdx.x;
    const int warp = tid >> 5, lane = tid & 31;
    const int g = lane >> 2, tg = lane & 3;
    const int wm = (warp >> 1) * 32, wn = (warp & 1) * 64;

    float acc[2][8][4];
#pragma unroll
    for (int mt = 0; mt < 2; ++mt)
#pragma unroll
        for (int j = 0; j < 8; ++j)
#pragma unroll
            for (int q = 0; q < 4; ++q) acc[mt][j][q] = 0.f;

    for (int k0 = 0; k0 < K; k0 += 32) {
        __syncthreads();
        // ---- A tile (128 rows x 32 k) -> As[m][k] as tf32 ----
#pragma unroll
        for (int it = 0; it < 4; ++it) {
            int f = tid + it * 256;      // 0..1023 float4 slots
            int row = f >> 3, kc4 = (f & 7) << 2;
            float4 v;
            if (MODE == 0) {
                int r = m0 + row;
                int c = k0 + kc4;
                int ktap = c >> 10, din = c & 1023;
                int b = r >> 6, gi = r & 63;
                v = *(const float4*)(g_xpos + ((b << 12) + (gi << 2) + ktap) * DIM + din);
            } else if (MODE == 1) {
                int c = k0 + kc4;
                const float* src = (c < 1024)
                                       ? (g_local + (m0 + row) * 1024 + c)
                                       : (g_glob + (m0 + row) * 1024 + (c - 1024));
                v = *(const float4*)src;
            } else {
                v = *(const float4*)(g_mixed + (m0 + row) * 1024 + k0 + kc4);
            }
            uint4 t;
            t.x = f2tf32(v.x); t.y = f2tf32(v.y);
            t.z = f2tf32(v.z); t.w = f2tf32(v.w);
            *(uint4*)&As[row * AS_STRIDE + kc4] = t;
        }
        // ---- B tile (32 k x 128 n) -> Bs[k][n] as tf32 ----
        if (MODE == 0) {
            // conv_w layout [dout][din][ktap]; c = ktap*1024 + din
#pragma unroll
            for (int it = 0; it < 16; ++it) {
                int f = tid + it * 256;  // 0..4095 scalars
                int kk = f >> 7, n = f & 127;
                int c = k0 + kk;
                int ktap = c >> 10, din = c & 1023;
                float v = Bw[(n0 + n) * 4096 + (din << 2) + ktap];
                Bs[kk * BS_STRIDE + n] = __uint_as_float(f2tf32(v));
            }
        } else {
#pragma unroll
            for (int it = 0; it < 4; ++it) {
                int f = tid + it * 256;  // 0..1023 float4 slots
                int kr = f >> 5, nc4 = (f & 31) << 2;
                float4 v = *(const float4*)(Bw + (k0 + kr) * 1024 + n0 + nc4);
                uint4 t;
                t.x = f2tf32(v.x); t.y = f2tf32(v.y);
                t.z = f2tf32(v.z); t.w = f2tf32(v.w);
                *(uint4*)&Bs[kr * BS_STRIDE + nc4] = t;
            }
        }
        __syncthreads();

#pragma unroll
        for (int s = 0; s < 4; ++s) {
            const int ks = s * 8;
            uint32_t bf[8][2];
#pragma unroll
            for (int j = 0; j < 8; ++j) {
                bf[j][0] = __float_as_uint(Bs[(ks + tg) * BS_STRIDE + wn + j * 8 + g]);
                bf[j][1] = __float_as_uint(Bs[(ks + tg + 4) * BS_STRIDE + wn + j * 8 + g]);
            }
#pragma unroll
            for (int mt = 0; mt < 2; ++mt) {
                int r0 = wm + mt * 16 + g;
                uint32_t a0 = __float_as_uint(As[r0 * AS_STRIDE + ks + tg]);
                uint32_t a1 = __float_as_uint(As[(r0 + 8) * AS_STRIDE + ks + tg]);
                uint32_t a2 = __float_as_uint(As[r0 * AS_STRIDE + ks + tg + 4]);
                uint32_t a3 = __float_as_uint(As[(r0 + 8) * AS_STRIDE + ks + tg + 4]);
#pragma unroll
                for (int j = 0; j < 8; ++j)
                    mma_tf32(acc[mt][j], a0, a1, a2, a3, bf[j][0], bf[j][1]);
            }
        }
    }

    // ---- epilogue: thread owns rows {g, g+8} x cols {2tg, 2tg+1} per (mt,j) ----
#pragma unroll
    for (int mt = 0; mt < 2; ++mt) {
#pragma unroll
        for (int j = 0; j < 8; ++j) {
            int col = n0 + wn + j * 8 + 2 * tg;
            int ra = m0 + wm + mt * 16 + g;
            int rb = ra + 8;
            float2 bz = *(const float2*)&bias[col];
            float z0x = acc[mt][j][0] + bz.x, z0y = acc[mt][j][1] + bz.y;
            float z1x = acc[mt][j][2] + bz.x, z1y = acc[mt][j][3] + bz.y;
            if (MODE == 0) {
                int oa = (((ra >> 6) << 7) | (ra & 63)) * 1024 + col;
                int ob2 = (((rb >> 6) << 7) | (rb & 63)) * 1024 + col;
                *(float2*)&g_gt[oa] = make_float2(z0x, z0y);
                *(float2*)&g_gt[ob2] = make_float2(z1x, z1y);
            } else if (MODE == 1) {
                int ia = ra * 1024 + col, ib = rb * 1024 + col;
                float2 la = *(const float2*)&g_local[ia];
                float2 lb = *(const float2*)&g_local[ib];
                float2 ga = *(const float2*)&g_glob[ia];
                float2 gb = *(const float2*)&g_glob[ib];
                float s0x = 1.0f / (1.0f + __expf(-z0x));
                float s0y = 1.0f / (1.0f + __expf(-z0y));
                float s1x = 1.0f / (1.0f + __expf(-z1x));
                float s1y = 1.0f / (1.0f + __expf(-z1y));
                *(float2*)&g_mixed[ia] =
                    make_float2(s0x * la.x + (1.f - s0x) * ga.x,
                                s0y * la.y + (1.f - s0y) * ga.y);
                *(float2*)&g_mixed[ib] =
                    make_float2(s1x * lb.x + (1.f - s1x) * gb.x,
                                s1y * lb.y + (1.f - s1y) * gb.y);
            } else {
                *(float2*)&Cext[ra * 1024 + col] = make_float2(z0x, z0y);
                *(float2*)&Cext[rb * 1024 + col] = make_float2(z1x, z1y);
            }
        }
    }
}

// ---------------- launch ----------------
extern "C" void kernel_launch(void* const* d_in, const int* in_sizes, int n_in,
                              void* d_out, int out_size) {
    const float* x = (const float*)d_in[0];
    const float* pe = (const float*)d_in[1];
    const float* gm = (const float*)d_in[2];
    const float* cw = (const float*)d_in[3];
    const float* cb = (const float*)d_in[4];
    const float* gw = (const float*)d_in[5];
    const float* gb = (const float*)d_in[6];
    const float* ow = (const float*)d_in[7];
    const float* ob = (const float*)d_in[8];
    float* out = (float*)d_out;

    cudaFuncSetAttribute((const void*)local_attn_kernel,
                         cudaFuncAttributeMaxDynamicSharedMemorySize, 69632);
    cudaFuncSetAttribute((const void*)global_attn_kernel,
                         cudaFuncAttributeMaxDynamicSharedMemorySize, 69632);

    add_pos_kernel<<<16384, 256>>>(x, pe);
    gemm_tf32<0><<<dim3(8, 2), 256>>>(cw, cb, nullptr);    // conv -> gt[:,0:64,:]
    gt_fill_kernel<<<256, 256>>>(gm);                       // gt[:,64:128,:]
    local_attn_kernel<<<4096, 256, 69632>>>();
    global_attn_kernel<<<4096, 256, 69632>>>();
    gemm_tf32<1><<<dim3(8, 128), 256>>>(gw, gb, nullptr);  // gate + mix
    gemm_tf32<2><<<dim3(8, 128), 256>>>(ow, ob, out);      // output projection
}

// round 4
// speedup vs baseline: 1.7555x; 1.6217x over previous
#include <cuda_runtime.h>
#include <cstdint>

#define NB 4
#define SEQ 4096
#define DIM 1024
#define NH 16
#define HDIM 64
#define WINS 512
#define NWIN 8
#define NGT 128

// ---------------- scratch (static device globals; no allocation) ----------------
__device__ float g_xpos[NB * SEQ * DIM];   // x + pos_emb
__device__ float g_local[NB * SEQ * DIM];  // local attention out (tf32-rounded)
__device__ float g_glob[NB * SEQ * DIM];   // global attention out (tf32-rounded)
__device__ float g_mixed[NB * SEQ * DIM];  // gated mix (tf32-rounded)
__device__ float g_gt[NB * NGT * DIM];     // [comp ; global_memory] per batch
__device__ float g_gwT[DIM * 2 * DIM];     // gate_w transposed [1024][2048] (tf32)
__device__ float g_owT[DIM * DIM];         // out_w transposed  [1024][1024] (tf32)

// ---------------- helpers ----------------
__device__ __forceinline__ uint32_t f2tf32(float x) {
    uint32_t r;
    asm("cvt.rna.tf32.f32 %0, %1;" : "=r"(r) : "f"(x));
    return r;
}
__device__ __forceinline__ float rnd_tf32(float x) {
    return __uint_as_float(f2tf32(x));
}
__device__ __forceinline__ uint32_t smem_u32(const void* p) {
    uint32_t a;
    asm("{ .reg .u64 t; cvta.to.shared.u64 t, %1; cvt.u32.u64 %0, t; }"
        : "=r"(a) : "l"(p));
    return a;
}
__device__ __forceinline__ void cp_async16(uint32_t dst, const float* src) {
    asm volatile("cp.async.cg.shared.global [%0], [%1], 16;"
                 :: "r"(dst), "l"(__cvta_generic_to_global(src)) : "memory");
}
__device__ __forceinline__ void cp_commit() {
    asm volatile("cp.async.commit_group;" ::: "memory");
}

__device__ __forceinline__ void mma_tf32(float* c, uint32_t a0, uint32_t a1,
                                         uint32_t a2, uint32_t a3,
                                         uint32_t b0, uint32_t b1) {
    asm volatile(
        "mma.sync.aligned.m16n8k8.row.col.f32.tf32.tf32.f32 "
        "{%0,%1,%2,%3}, {%4,%5,%6,%7}, {%8,%9}, {%0,%1,%2,%3};"
        : "+f"(c[0]), "+f"(c[1]), "+f"(c[2]), "+f"(c[3])
        : "r"(a0), "r"(a1), "r"(a2), "r"(a3), "r"(b0), "r"(b1));
}

// ---------------- kernel 1: x + pos_emb ----------------
__global__ __launch_bounds__(256) void add_pos_kernel(const float* __restrict__ x,
                                                      const float* __restrict__ pe) {
    int i = blockIdx.x * 256 + threadIdx.x;
    float4 a = ((const float4*)x)[i];
    float4 p = ((const float4*)pe)[i & 1048575];
    float4 r;
    r.x = a.x + p.x; r.y = a.y + p.y; r.z = a.z + p.z; r.w = a.w + p.w;
    ((float4*)g_xpos)[i] = r;
}

// ---------------- fill global_memory half of gt ----------------
__global__ __launch_bounds__(256) void gt_fill_kernel(const float* __restrict__ gm) {
    int i = blockIdx.x * 256 + threadIdx.x;
    float4 v = ((const float4*)gm)[i & 16383];
    ((float4*)g_gt)[(i >> 14) * 32768 + 16384 + (i & 16383)] = v;
}

// ---------------- transpose + tf32 round: in[K][N] -> out[N][K] ----------------
__global__ __launch_bounds__(256) void transpose_kernel(const float* __restrict__ in,
                                                        float* __restrict__ out,
                                                        int K, int N) {
    __shared__ float t[32][33];
    int bx = blockIdx.x * 32;  // n
    int by = blockIdx.y * 32;  // k
    int x = threadIdx.x & 31, y = threadIdx.x >> 5;  // 32x8
#pragma unroll
    for (int i = 0; i < 32; i += 8) t[y + i][x] = in[(by + y + i) * N + bx + x];
    __syncthreads();
#pragma unroll
    for (int i = 0; i < 32; i += 8)
        out[(bx + y + i) * K + by + x] = rnd_tf32(t[x][y + i]);
}

// ---------------- flash attention core (64 q-rows per block, 256 threads) ----------------
__device__ __forceinline__ void flash_core(const float* __restrict__ qb,
                                           const float* __restrict__ kb,
                                           float* __restrict__ obp, int nkt) {
    extern __shared__ float sm[];
    float* Qt = sm;
    float* Kt = sm + 4352;
    float* Vs = sm + 8704;
    float* Pt = sm + 13056;
    const int tid = threadIdx.x, tx = tid & 15, ty = tid >> 4;
    const float scale = 0.125f;

#pragma unroll
    for (int it = 0; it < 4; ++it) {
        int f = tid + it * 256;
        int row = f >> 4, c4 = (f & 15) << 2;
        float4 v = *(const float4*)(qb + row * DIM + c4);
        Qt[(c4 + 0) * 68 + row] = v.x * scale;
        Qt[(c4 + 1) * 68 + row] = v.y * scale;
        Qt[(c4 + 2) * 68 + row] = v.z * scale;
        Qt[(c4 + 3) * 68 + row] = v.w * scale;
    }
    float m[4], l[4], acc[4][4];
#pragma unroll
    for (int i = 0; i < 4; i++) {
        m[i] = -1e30f; l[i] = 0.f;
#pragma unroll
        for (int j = 0; j < 4; j++) acc[i][j] = 0.f;
    }

    for (int kt = 0; kt < nkt; ++kt) {
        __syncthreads();
#pragma unroll
        for (int it = 0; it < 4; ++it) {
            int f = tid + it * 256;
            int row = f >> 4, c4 = (f & 15) << 2;
            float4 v = *(const float4*)(kb + (kt * 64 + row) * DIM + c4);
            Kt[(c4 + 0) * 68 + row] = v.x;
            Kt[(c4 + 1) * 68 + row] = v.y;
            Kt[(c4 + 2) * 68 + row] = v.z;
            Kt[(c4 + 3) * 68 + row] = v.w;
            *(float4*)(Vs + row * 68 + c4) = v;
        }
        __syncthreads();

        float s[4][4];
#pragma unroll
        for (int i = 0; i < 4; i++)
#pragma unroll
            for (int j = 0; j < 4; j++) s[i][j] = 0.f;
#pragma unroll 8
        for (int d = 0; d < 64; ++d) {
            float4 qv = *(const float4*)(Qt + d * 68 + (ty << 2));
            float4 kv = *(const float4*)(Kt + d * 68 + (tx << 2));
            float qa[4] = {qv.x, qv.y, qv.z, qv.w};
            float ka[4] = {kv.x, kv.y, kv.z, kv.w};
#pragma unroll
            for (int i = 0; i < 4; i++)
#pragma unroll
                for (int j = 0; j < 4; j++) s[i][j] += qa[i] * ka[j];
        }

        float rmax[4];
#pragma unroll
        for (int i = 0; i < 4; i++)
            rmax[i] = fmaxf(fmaxf(s[i][0], s[i][1]), fmaxf(s[i][2], s[i][3]));
#pragma unroll
        for (int off = 8; off >= 1; off >>= 1) {
#pragma unroll
            for (int i = 0; i < 4; i++)
                rmax[i] = fmaxf(rmax[i], __shfl_xor_sync(0xffffffffu, rmax[i], off));
        }
        float psum[4];
#pragma unroll
        for (int i = 0; i < 4; i++) {
            float mnew = fmaxf(m[i], rmax[i]);
            float corr = __expf(m[i] - mnew);
            m[i] = mnew;
#pragma unroll
            for (int j = 0; j < 4; j++) s[i][j] = __expf(s[i][j] - mnew);
            psum[i] = s[i][0] + s[i][1] + s[i][2] + s[i][3];
            l[i] *= corr;
#pragma unroll
            for (int j = 0; j < 4; j++) acc[i][j] *= corr;
        }
#pragma unroll
        for (int off = 8; off >= 1; off >>= 1) {
#pragma unroll
            for (int i = 0; i < 4; i++)
                psum[i] += __shfl_xor_sync(0xffffffffu, psum[i], off);
        }
#pragma unroll
        for (int i = 0; i < 4; i++) l[i] += psum[i];

#pragma unroll
        for (int j = 0; j < 4; j++) {
            float4 pv = make_float4(s[0][j], s[1][j], s[2][j], s[3][j]);
            *(float4*)(Pt + ((tx << 2) + j) * 68 + (ty << 2)) = pv;
        }
        __syncthreads();
#pragma unroll 8
        for (int k2 = 0; k2 < 64; ++k2) {
            float4 pv = *(const float4*)(Pt + k2 * 68 + (ty << 2));
            float4 vv = *(const float4*)(Vs + k2 * 68 + (tx << 2));
            float pa[4] = {pv.x, pv.y, pv.z, pv.w};
            float va[4] = {vv.x, vv.y, vv.z, vv.w};
#pragma unroll
            for (int i = 0; i < 4; i++)
#pragma unroll
                for (int j = 0; j < 4; j++) acc[i][j] += pa[i] * va[j];
        }
    }

    // outputs are GEMM-A sources downstream: store tf32(RNA)-rounded
#pragma unroll
    for (int i = 0; i < 4; i++) {
        float inv = 1.0f / l[i];
        float4 o;
        o.x = rnd_tf32(acc[i][0] * inv);
        o.y = rnd_tf32(acc[i][1] * inv);
        o.z = rnd_tf32(acc[i][2] * inv);
        o.w = rnd_tf32(acc[i][3] * inv);
        *(float4*)(obp + ((ty << 2) + i) * DIM + (tx << 2)) = o;
    }
}

__global__ __launch_bounds__(256) void local_attn_kernel() {
    int bx = blockIdx.x;
    int qt = bx & 7;
    int h = (bx >> 3) & 15;
    int w = (bx >> 7) & 7;
    int b = bx >> 10;
    const float* base = g_xpos + (b * SEQ + w * WINS) * DIM + h * HDIM;
    const float* qb = base + (qt * 64) * DIM;
    float* ob = g_local + (b * SEQ + w * WINS + qt * 64) * DIM + h * HDIM;
    flash_core(qb, base, ob, 8);
}

__global__ __launch_bounds__(256) void global_attn_kernel() {
    int bx = blockIdx.x;
    int qt = bx & 63;
    int h = (bx >> 6) & 15;
    int b = bx >> 10;
    const float* qb = g_xpos + (b * SEQ + qt * 64) * DIM + h * HDIM;
    const float* kb = g_gt + (b * NGT) * DIM + h * HDIM;
    float* ob = g_glob + (b * SEQ + qt * 64) * DIM + h * HDIM;
    flash_core(qb, kb, ob, 2);
}

// ==================== pipelined tf32 mma GEMM, 128x128 tile, KT=32 ====================
// cp.async double-buffered; A and B smem tiles are [row][k] stride 36 (144B rows,
// 16B-aligned for cp.async, conflict-free scalar fragment LDS).
// MODE 1: z = [local|glob] @ gate_w + gate_b; mixed = sig(z)*local+(1-sig)*glob (K=2048)
// MODE 2: out = mixed @ out_w + out_b -> Cext (K=1024)
#define STG_F 9216  // floats per stage: A 128*36 + B 128*36
#define GP_SMEM (2 * STG_F * 4)

template <int MODE>
__device__ __forceinline__ void gp_load(float* sm, int s, int m0, int n0, int k0,
                                        const float* Bsrc, int tid) {
    float* A = sm + s * STG_F;
    float* B = A + 4608;
    constexpr int KTOT = (MODE == 1) ? 2048 : 1024;
#pragma unroll
    for (int t = 0; t < 4; ++t) {
        int id = tid + t * 256;          // 0..1023
        int r = id >> 3, q = id & 7;     // row, 16B segment
        int kk = k0 + q * 4;
        const float* src;
        if (MODE == 1) {
            src = (kk < 1024) ? g_local + (m0 + r) * 1024 + kk
                              : g_glob + (m0 + r) * 1024 + (kk - 1024);
        } else {
            src = g_mixed + (m0 + r) * 1024 + kk;
        }
        cp_async16(smem_u32(A + r * 36 + q * 4), src);
    }
#pragma unroll
    for (int t = 0; t < 4; ++t) {
        int id = tid + t * 256;
        int r = id >> 3, q = id & 7;
        cp_async16(smem_u32(B + r * 36 + q * 4), Bsrc + (n0 + r) * KTOT + k0 + q * 4);
    }
    cp_commit();
}

template <int MODE>
__global__ __launch_bounds__(256) void gemm_pipe(const float* __restrict__ bias,
                                                 float* __restrict__ Cext) {
    constexpr int K = (MODE == 1) ? 2048 : 1024;
    constexpr int NIT = K / 32;
    extern __shared__ float sm[];
    const int tid = threadIdx.x;
    const int warp = tid >> 5, lane = tid & 31;
    const int g = lane >> 2, tg = lane & 3;
    const int wm = (warp >> 1) * 32, wn = (warp & 1) * 64;
    const int m0 = blockIdx.y * 128, n0 = blockIdx.x * 128;
    const float* Bsrc = (MODE == 1) ? g_gwT : g_owT;

    float acc[2][8][4];
#pragma unroll
    for (int mt = 0; mt < 2; ++mt)
#pragma unroll
        for (int j = 0; j < 8; ++j)
#pragma unroll
            for (int q = 0; q < 4; ++q) acc[mt][j][q] = 0.f;

    gp_load<MODE>(sm, 0, m0, n0, 0, Bsrc, tid);

    for (int i = 0; i < NIT; ++i) {
        if (i + 1 < NIT) {
            gp_load<MODE>(sm, (i + 1) & 1, m0, n0, (i + 1) * 32, Bsrc, tid);
            asm volatile("cp.async.wait_group 1;" ::: "memory");
        } else {
            asm volatile("cp.async.wait_group 0;" ::: "memory");
        }
        __syncthreads();

        const float* As = sm + (i & 1) * STG_F;
        const float* Bs = As + 4608;
#pragma unroll
        for (int s = 0; s < 4; ++s) {
            const int ks = s * 8;
            uint32_t bf[8][2];
#pragma unroll
            for (int j = 0; j < 8; ++j) {
                int n = wn + j * 8 + g;
                bf[j][0] = __float_as_uint(Bs[n * 36 + ks + tg]);
                bf[j][1] = __float_as_uint(Bs[n * 36 + ks + tg + 4]);
            }
#pragma unroll
            for (int mt = 0; mt < 2; ++mt) {
                int r0 = wm + mt * 16 + g;
                uint32_t a0 = __float_as_uint(As[r0 * 36 + ks + tg]);
                uint32_t a1 = __float_as_uint(As[(r0 + 8) * 36 + ks + tg]);
                uint32_t a2 = __float_as_uint(As[r0 * 36 + ks + tg + 4]);
                uint32_t a3 = __float_as_uint(As[(r0 + 8) * 36 + ks + tg + 4]);
#pragma unroll
                for (int j = 0; j < 8; ++j)
                    mma_tf32(acc[mt][j], a0, a1, a2, a3, bf[j][0], bf[j][1]);
            }
        }
        __syncthreads();
    }

    // ---- epilogue ----
#pragma unroll
    for (int mt = 0; mt < 2; ++mt) {
#pragma unroll
        for (int j = 0; j < 8; ++j) {
            int col = n0 + wn + j * 8 + 2 * tg;
            int ra = m0 + wm + mt * 16 + g;
            int rb = ra + 8;
            float2 bz = *(const float2*)&bias[col];
            float z0x = acc[mt][j][0] + bz.x, z0y = acc[mt][j][1] + bz.y;
            float z1x = acc[mt][j][2] + bz.x, z1y = acc[mt][j][3] + bz.y;
            if (MODE == 1) {
                int ia = ra * 1024 + col, ib = rb * 1024 + col;
                float2 la = *(const float2*)&g_local[ia];
                float2 lb = *(const float2*)&g_local[ib];
                float2 ga = *(const float2*)&g_glob[ia];
                float2 gb = *(const float2*)&g_glob[ib];
                float s0x = 1.0f / (1.0f + __expf(-z0x));
                float s0y = 1.0f / (1.0f + __expf(-z0y));
                float s1x = 1.0f / (1.0f + __expf(-z1x));
                float s1y = 1.0f / (1.0f + __expf(-z1y));
                // mixed feeds the out GEMM as A: store tf32(RNA)-rounded
                *(float2*)&g_mixed[ia] =
                    make_float2(rnd_tf32(s0x * la.x + (1.f - s0x) * ga.x),
                                rnd_tf32(s0y * la.y + (1.f - s0y) * ga.y));
                *(float2*)&g_mixed[ib] =
                    make_float2(rnd_tf32(s1x * lb.x + (1.f - s1x) * gb.x),
                                rnd_tf32(s1y * lb.y + (1.f - s1y) * gb.y));
            } else {
                *(float2*)&Cext[ra * 1024 + col] = make_float2(z0x, z0y);
                *(float2*)&Cext[rb * 1024 + col] = make_float2(z1x, z1y);
            }
        }
    }
}

// ---------------- legacy tf32 mma GEMM for the small conv (M=256, K=4096) ----------------
#define AS_STRIDE 36
#define BS_STRIDE 136
__global__ __launch_bounds__(256) void conv_gemm(const float* __restrict__ Bw,
                                                 const float* __restrict__ bias) {
    constexpr int K = 4096;
    __shared__ float As[128 * AS_STRIDE];
    __shared__ float Bs[32 * BS_STRIDE];
    const int m0 = blockIdx.y * 128, n0 = blockIdx.x * 128;
    const int tid = threadIdx.x;
    const int warp = tid >> 5, lane = tid & 31;
    const int g = lane >> 2, tg = lane & 3;
    const int wm = (warp >> 1) * 32, wn = (warp & 1) * 64;

    float acc[2][8][4];
#pragma unroll
    for (int mt = 0; mt < 2; ++mt)
#pragma unroll
        for (int j = 0; j < 8; ++j)
#pragma unroll
            for (int q = 0; q < 4; ++q) acc[mt][j][q] = 0.f;

    for (int k0 = 0; k0 < K; k0 += 32) {
        __syncthreads();
#pragma unroll
        for (int it = 0; it < 4; ++it) {
            int f = tid + it * 256;
            int row = f >> 3, kc4 = (f & 7) << 2;
            int r = m0 + row;
            int c = k0 + kc4;
            int ktap = c >> 10, din = c & 1023;
            int b = r >> 6, gi = r & 63;
            float4 v = *(const float4*)(g_xpos + ((b << 12) + (gi << 2) + ktap) * DIM + din);
            uint4 t;
            t.x = f2tf32(v.x); t.y = f2tf32(v.y); t.z = f2tf32(v.z); t.w = f2tf32(v.w);
            *(uint4*)&As[row * AS_STRIDE + kc4] = t;
        }
#pragma unroll
        for (int it = 0; it < 16; ++it) {
            int f = tid + it * 256;
            int kk = f >> 7, n = f & 127;
            int c = k0 + kk;
            int ktap = c >> 10, din = c & 1023;
            float v = Bw[(n0 + n) * 4096 + (din << 2) + ktap];
            Bs[kk * BS_STRIDE + n] = __uint_as_float(f2tf32(v));
        }
        __syncthreads();
#pragma unroll
        for (int s = 0; s < 4; ++s) {
            const int ks = s * 8;
            uint32_t bf[8][2];
#pragma unroll
            for (int j = 0; j < 8; ++j) {
                bf[j][0] = __float_as_uint(Bs[(ks + tg) * BS_STRIDE + wn + j * 8 + g]);
                bf[j][1] = __float_as_uint(Bs[(ks + tg + 4) * BS_STRIDE + wn + j * 8 + g]);
            }
#pragma unroll
            for (int mt = 0; mt < 2; ++mt) {
                int r0 = wm + mt * 16 + g;
                uint32_t a0 = __float_as_uint(As[r0 * AS_STRIDE + ks + tg]);
                uint32_t a1 = __float_as_uint(As[(r0 + 8) * AS_STRIDE + ks + tg]);
                uint32_t a2 = __float_as_uint(As[r0 * AS_STRIDE + ks + tg + 4]);
                uint32_t a3 = __float_as_uint(As[(r0 + 8) * AS_STRIDE + ks + tg + 4]);
#pragma unroll
                for (int j = 0; j < 8; ++j)
                    mma_tf32(acc[mt][j], a0, a1, a2, a3, bf[j][0], bf[j][1]);
            }
        }
    }
#pragma unroll
    for (int mt = 0; mt < 2; ++mt) {
#pragma unroll
        for (int j = 0; j < 8; ++j) {
            int col = n0 + wn + j * 8 + 2 * tg;
            int ra = m0 + wm + mt * 16 + g;
            int rb = ra + 8;
            float2 bz = *(const float2*)&bias[col];
            int oa = (((ra >> 6) << 7) | (ra & 63)) * 1024 + col;
            int ob2 = (((rb >> 6) << 7) | (rb & 63)) * 1024 + col;
            *(float2*)&g_gt[oa] = make_float2(acc[mt][j][0] + bz.x, acc[mt][j][1] + bz.y);
            *(float2*)&g_gt[ob2] = make_float2(acc[mt][j][2] + bz.x, acc[mt][j][3] + bz.y);
        }
    }
}

// ---------------- launch ----------------
extern "C" void kernel_launch(void* const* d_in, const int* in_sizes, int n_in,
                              void* d_out, int out_size) {
    const float* x = (const float*)d_in[0];
    const float* pe = (const float*)d_in[1];
    const float* gm = (const float*)d_in[2];
    const float* cw = (const float*)d_in[3];
    const float* cb = (const float*)d_in[4];
    const float* gw = (const float*)d_in[5];
    const float* gb = (const float*)d_in[6];
    const float* ow = (const float*)d_in[7];
    const float* ob = (const float*)d_in[8];
    float* out = (float*)d_out;

    cudaFuncSetAttribute((const void*)local_attn_kernel,
                         cudaFuncAttributeMaxDynamicSharedMemorySize, 69632);
    cudaFuncSetAttribute((const void*)global_attn_kernel,
                         cudaFuncAttributeMaxDynamicSharedMemorySize, 69632);
    cudaFuncSetAttribute((const void*)gemm_pipe<1>,
                         cudaFuncAttributeMaxDynamicSharedMemorySize, GP_SMEM);
    cudaFuncSetAttribute((const void*)gemm_pipe<2>,
                         cudaFuncAttributeMaxDynamicSharedMemorySize, GP_SMEM);

    float* gwT;
    float* owT;
    cudaGetSymbolAddress((void**)&gwT, g_gwT);
    cudaGetSymbolAddress((void**)&owT, g_owT);

    add_pos_kernel<<<16384, 256>>>(x, pe);
    transpose_kernel<<<dim3(32, 64), 256>>>(gw, gwT, 2048, 1024);
    transpose_kernel<<<dim3(32, 32), 256>>>(ow, owT, 1024, 1024);
    conv_gemm<<<dim3(8, 2), 256>>>(cw, cb);
    gt_fill_kernel<<<256, 256>>>(gm);
    local_attn_kernel<<<4096, 256, 69632>>>();
    global_attn_kernel<<<4096, 256, 69632>>>();
    gemm_pipe<1><<<dim3(8, 128), 256, GP_SMEM>>>(gb, nullptr);  // gate + mix
    gemm_pipe<2><<<dim3(8, 128), 256, GP_SMEM>>>(ob, out);      // output projection
}

// round 5
// speedup vs baseline: 2.1580x; 1.2293x over previous
#include <cuda_runtime.h>
#include <cstdint>

#define NB 4
#define SEQ 4096
#define DIM 1024
#define NH 16
#define HDIM 64
#define WINS 512
#define NWIN 8
#define NGT 128

// ---------------- scratch (static device globals; no allocation) ----------------
__device__ float g_xpos[NB * SEQ * DIM];   // x + pos_emb
__device__ float g_local[NB * SEQ * DIM];  // local attention out (tf32-rounded)
__device__ float g_glob[NB * SEQ * DIM];   // global attention out (tf32-rounded)
__device__ float g_mixed[NB * SEQ * DIM];  // gated mix (tf32-rounded)
__device__ float g_gt[NB * NGT * DIM];     // [comp ; global_memory] per batch
__device__ float g_gwT[DIM * 2 * DIM];     // gate_w transposed [1024][2048] (tf32)
__device__ float g_owT[DIM * DIM];         // out_w transposed  [1024][1024] (tf32)
__device__ float g_convA[256 * 4096];      // im2col A (tf32-rounded)
__device__ float g_cwT[DIM * 4096];        // conv_w rearranged [dout][ktap*1024+din]
__device__ float g_comp[256 * DIM];        // conv split-K accumulator

// ---------------- helpers ----------------
__device__ __forceinline__ uint32_t f2tf32(float x) {
    uint32_t r;
    asm("cvt.rna.tf32.f32 %0, %1;" : "=r"(r) : "f"(x));
    return r;
}
__device__ __forceinline__ float rnd_tf32(float x) {
    return __uint_as_float(f2tf32(x));
}
__device__ __forceinline__ uint32_t smem_u32(const void* p) {
    uint32_t a;
    asm("{ .reg .u64 t; cvta.to.shared.u64 t, %1; cvt.u32.u64 %0, t; }"
        : "=r"(a) : "l"(p));
    return a;
}
__device__ __forceinline__ void cp_async16(uint32_t dst, const float* src) {
    asm volatile("cp.async.cg.shared.global [%0], [%1], 16;"
                 :: "r"(dst), "l"(__cvta_generic_to_global(src)) : "memory");
}
__device__ __forceinline__ void cp_commit() {
    asm volatile("cp.async.commit_group;" ::: "memory");
}

// fast exp on fma/alu pipes (no MUFU). |rel err| ~2e-6 for x <= 0.
__device__ __forceinline__ float fexp(float x) {
    float z = fmaxf(x, -87.3365f) * 1.4426950408889634f;  // log2(e)
    float s = z + 12582912.0f;                            // round-to-nearest int
    int n = __float_as_int(s) - 0x4b400000;
    float f = z - (s - 12582912.0f);                      // f in [-0.5, 0.5]
    float p = 1.3371542e-3f;
    p = fmaf(p, f, 9.6181291e-3f);
    p = fmaf(p, f, 5.5504109e-2f);
    p = fmaf(p, f, 2.4022651e-1f);
    p = fmaf(p, f, 6.9314718e-1f);
    p = fmaf(p, f, 1.0f);
    return __int_as_float(__float_as_int(p) + (n << 23));
}

__device__ __forceinline__ void mma_tf32(float* c, uint32_t a0, uint32_t a1,
                                         uint32_t a2, uint32_t a3,
                                         uint32_t b0, uint32_t b1) {
    asm volatile(
        "mma.sync.aligned.m16n8k8.row.col.f32.tf32.tf32.f32 "
        "{%0,%1,%2,%3}, {%4,%5,%6,%7}, {%8,%9}, {%0,%1,%2,%3};"
        : "+f"(c[0]), "+f"(c[1]), "+f"(c[2]), "+f"(c[3])
        : "r"(a0), "r"(a1), "r"(a2), "r"(a3), "r"(b0), "r"(b1));
}

// ---------------- kernel: x + pos_emb ----------------
__global__ __launch_bounds__(256) void add_pos_kernel(const float* __restrict__ x,
                                                      const float* __restrict__ pe) {
    int i = blockIdx.x * 256 + threadIdx.x;
    float4 a = ((const float4*)x)[i];
    float4 p = ((const float4*)pe)[i & 1048575];
    float4 r;
    r.x = a.x + p.x; r.y = a.y + p.y; r.z = a.z + p.z; r.w = a.w + p.w;
    ((float4*)g_xpos)[i] = r;
}

// ---------------- fill global_memory half of gt ----------------
__global__ __launch_bounds__(256) void gt_fill_kernel(const float* __restrict__ gm) {
    int i = blockIdx.x * 256 + threadIdx.x;
    float4 v = ((const float4*)gm)[i & 16383];
    ((float4*)g_gt)[(i >> 14) * 32768 + 16384 + (i & 16383)] = v;
}

// ---------------- transpose + tf32 round: in[K][N] -> out[N][K] ----------------
__global__ __launch_bounds__(256) void transpose_kernel(const float* __restrict__ in,
                                                        float* __restrict__ out,
                                                        int K, int N) {
    __shared__ float t[32][33];
    int bx = blockIdx.x * 32;
    int by = blockIdx.y * 32;
    int x = threadIdx.x & 31, y = threadIdx.x >> 5;
#pragma unroll
    for (int i = 0; i < 32; i += 8) t[y + i][x] = in[(by + y + i) * N + bx + x];
    __syncthreads();
#pragma unroll
    for (int i = 0; i < 32; i += 8)
        out[(bx + y + i) * K + by + x] = rnd_tf32(t[x][y + i]);
}

// ---------------- conv pre-transforms ----------------
// im2col: A[(b*64+g)][ktap*1024+din] = xpos[b][4g+ktap][din], tf32-rounded
__global__ __launch_bounds__(256) void im2col_kernel() {
    int i = blockIdx.x * 256 + threadIdx.x;  // 262144 float4s
    int r = i >> 10, q = i & 1023;
    int c4 = q << 2;
    int ktap = c4 >> 10, din = c4 & 1023;
    int b = r >> 6, g = r & 63;
    float4 v = *(const float4*)(g_xpos + ((b << 12) + (g << 2) + ktap) * DIM + din);
    float4 o;
    o.x = rnd_tf32(v.x); o.y = rnd_tf32(v.y); o.z = rnd_tf32(v.z); o.w = rnd_tf32(v.w);
    *(float4*)(g_convA + r * 4096 + c4) = o;
}

// conv_w [dout][din][ktap] -> g_cwT[dout][ktap*1024+din], tf32-rounded
__global__ __launch_bounds__(256) void cw_rearrange_kernel(const float* __restrict__ cw) {
    int i = blockIdx.x * 256 + threadIdx.x;  // 1048576 float4s
    int dout = i >> 10, q = i & 1023;
    int c4 = q << 2;
    int ktap = c4 >> 10, din = c4 & 1023;
    const float* base = cw + dout * 4096 + din * 4 + ktap;
    float4 o;
    o.x = rnd_tf32(base[0]);
    o.y = rnd_tf32(base[4]);
    o.z = rnd_tf32(base[8]);
    o.w = rnd_tf32(base[12]);
    *(float4*)(g_cwT + dout * 4096 + c4) = o;
}

__global__ __launch_bounds__(256) void zero_comp_kernel() {
    int i = blockIdx.x * 256 + threadIdx.x;  // 65536 float4s
    ((float4*)g_comp)[i] = make_float4(0.f, 0.f, 0.f, 0.f);
}

// comp + bias -> gt rows (b*128 + g)
__global__ __launch_bounds__(256) void conv_scatter_kernel(const float* __restrict__ cb) {
    int i = blockIdx.x * 256 + threadIdx.x;  // 65536 float4s
    int r = i >> 8, c4 = (i & 255) << 2;
    float4 v = *(const float4*)(g_comp + r * 1024 + c4);
    float4 b = *(const float4*)(cb + c4);
    v.x += b.x; v.y += b.y; v.z += b.z; v.w += b.w;
    int outr = ((r >> 6) << 7) | (r & 63);
    *(float4*)(g_gt + outr * 1024 + c4) = v;
}

// ---------------- flash attention core (64 q-rows per block, 256 threads) ----------------
__device__ __forceinline__ void flash_core(const float* __restrict__ qb,
                                           const float* __restrict__ kb,
                                           float* __restrict__ obp, int nkt) {
    extern __shared__ float sm[];
    float* Qt = sm;
    float* Kt = sm + 4352;
    float* Vs = sm + 8704;
    float* Pt = sm + 13056;
    const int tid = threadIdx.x, tx = tid & 15, ty = tid >> 4;
    const float scale = 0.125f;

#pragma unroll
    for (int it = 0; it < 4; ++it) {
        int f = tid + it * 256;
        int row = f >> 4, c4 = (f & 15) << 2;
        float4 v = *(const float4*)(qb + row * DIM + c4);
        Qt[(c4 + 0) * 68 + row] = v.x * scale;
        Qt[(c4 + 1) * 68 + row] = v.y * scale;
        Qt[(c4 + 2) * 68 + row] = v.z * scale;
        Qt[(c4 + 3) * 68 + row] = v.w * scale;
    }
    float m[4], l[4], acc[4][4];
#pragma unroll
    for (int i = 0; i < 4; i++) {
        m[i] = -1e30f; l[i] = 0.f;
#pragma unroll
        for (int j = 0; j < 4; j++) acc[i][j] = 0.f;
    }

    for (int kt = 0; kt < nkt; ++kt) {
        __syncthreads();
#pragma unroll
        for (int it = 0; it < 4; ++it) {
            int f = tid + it * 256;
            int row = f >> 4, c4 = (f & 15) << 2;
            float4 v = *(const float4*)(kb + (kt * 64 + row) * DIM + c4);
            Kt[(c4 + 0) * 68 + row] = v.x;
            Kt[(c4 + 1) * 68 + row] = v.y;
            Kt[(c4 + 2) * 68 + row] = v.z;
            Kt[(c4 + 3) * 68 + row] = v.w;
            *(float4*)(Vs + row * 68 + c4) = v;
        }
        __syncthreads();

        float s[4][4];
#pragma unroll
        for (int i = 0; i < 4; i++)
#pragma unroll
            for (int j = 0; j < 4; j++) s[i][j] = 0.f;
#pragma unroll 8
        for (int d = 0; d < 64; ++d) {
            float4 qv = *(const float4*)(Qt + d * 68 + (ty << 2));
            float4 kv = *(const float4*)(Kt + d * 68 + (tx << 2));
            float qa[4] = {qv.x, qv.y, qv.z, qv.w};
            float ka[4] = {kv.x, kv.y, kv.z, kv.w};
#pragma unroll
            for (int i = 0; i < 4; i++)
#pragma unroll
                for (int j = 0; j < 4; j++) s[i][j] += qa[i] * ka[j];
        }

        float rmax[4];
#pragma unroll
        for (int i = 0; i < 4; i++)
            rmax[i] = fmaxf(fmaxf(s[i][0], s[i][1]), fmaxf(s[i][2], s[i][3]));
#pragma unroll
        for (int off = 8; off >= 1; off >>= 1) {
#pragma unroll
            for (int i = 0; i < 4; i++)
                rmax[i] = fmaxf(rmax[i], __shfl_xor_sync(0xffffffffu, rmax[i], off));
        }
        float psum[4];
#pragma unroll
        for (int i = 0; i < 4; i++) {
            float mnew = fmaxf(m[i], rmax[i]);
            float corr = fexp(m[i] - mnew);
            m[i] = mnew;
#pragma unroll
            for (int j = 0; j < 4; j++) s[i][j] = fexp(s[i][j] - mnew);
            psum[i] = s[i][0] + s[i][1] + s[i][2] + s[i][3];
            l[i] *= corr;
#pragma unroll
            for (int j = 0; j < 4; j++) acc[i][j] *= corr;
        }
#pragma unroll
        for (int off = 8; off >= 1; off >>= 1) {
#pragma unroll
            for (int i = 0; i < 4; i++)
                psum[i] += __shfl_xor_sync(0xffffffffu, psum[i], off);
        }
#pragma unroll
        for (int i = 0; i < 4; i++) l[i] += psum[i];

#pragma unroll
        for (int j = 0; j < 4; j++) {
            float4 pv = make_float4(s[0][j], s[1][j], s[2][j], s[3][j]);
            *(float4*)(Pt + ((tx << 2) + j) * 68 + (ty << 2)) = pv;
        }
        __syncthreads();
#pragma unroll 8
        for (int k2 = 0; k2 < 64; ++k2) {
            float4 pv = *(const float4*)(Pt + k2 * 68 + (ty << 2));
            float4 vv = *(const float4*)(Vs + k2 * 68 + (tx << 2));
            float pa[4] = {pv.x, pv.y, pv.z, pv.w};
            float va[4] = {vv.x, vv.y, vv.z, vv.w};
#pragma unroll
            for (int i = 0; i < 4; i++)
#pragma unroll
                for (int j = 0; j < 4; j++) acc[i][j] += pa[i] * va[j];
        }
    }

    // outputs are GEMM-A sources downstream: store tf32(RNA)-rounded
#pragma unroll
    for (int i = 0; i < 4; i++) {
        float inv = 1.0f / l[i];
        float4 o;
        o.x = rnd_tf32(acc[i][0] * inv);
        o.y = rnd_tf32(acc[i][1] * inv);
        o.z = rnd_tf32(acc[i][2] * inv);
        o.w = rnd_tf32(acc[i][3] * inv);
        *(float4*)(obp + ((ty << 2) + i) * DIM + (tx << 2)) = o;
    }
}

__global__ __launch_bounds__(256) void local_attn_kernel() {
    int bx = blockIdx.x;
    int qt = bx & 7;
    int h = (bx >> 3) & 15;
    int w = (bx >> 7) & 7;
    int b = bx >> 10;
    const float* base = g_xpos + (b * SEQ + w * WINS) * DIM + h * HDIM;
    const float* qb = base + (qt * 64) * DIM;
    float* ob = g_local + (b * SEQ + w * WINS + qt * 64) * DIM + h * HDIM;
    flash_core(qb, base, ob, 8);
}

__global__ __launch_bounds__(256) void global_attn_kernel() {
    int bx = blockIdx.x;
    int qt = bx & 63;
    int h = (bx >> 6) & 15;
    int b = bx >> 10;
    const float* qb = g_xpos + (b * SEQ + qt * 64) * DIM + h * HDIM;
    const float* kb = g_gt + (b * NGT) * DIM + h * HDIM;
    float* ob = g_glob + (b * SEQ + qt * 64) * DIM + h * HDIM;
    flash_core(qb, kb, ob, 2);
}

// ==================== pipelined tf32 mma GEMM, 128x128 tile, KT=32 ====================
// MODE 0: conv split-K: g_convA[256][4096] @ g_cwT^T, K-slice 512 per z-block,
//         atomicAdd into g_comp (no bias).
// MODE 1: z = [local|glob] @ gate_w + gate_b; mixed = sig(z)*local+(1-sig)*glob (K=2048)
// MODE 2: out = mixed @ out_w + out_b -> Cext (K=1024)
#define STG_F 9216
#define GP_SMEM (2 * STG_F * 4)

template <int MODE>
__device__ __forceinline__ void gp_load(float* sm, int s, int m0, int n0, int k0,
                                        const float* Bsrc, int tid) {
    float* A = sm + s * STG_F;
    float* B = A + 4608;
    constexpr int KTOT = (MODE == 0) ? 4096 : (MODE == 1) ? 2048 : 1024;
#pragma unroll
    for (int t = 0; t < 4; ++t) {
        int id = tid + t * 256;
        int r = id >> 3, q = id & 7;
        int kk = k0 + q * 4;
        const float* src;
        if (MODE == 0) {
            src = g_convA + (m0 + r) * 4096 + kk;
        } else if (MODE == 1) {
            src = (kk < 1024) ? g_local + (m0 + r) * 1024 + kk
                              : g_glob + (m0 + r) * 1024 + (kk - 1024);
        } else {
            src = g_mixed + (m0 + r) * 1024 + kk;
        }
        cp_async16(smem_u32(A + r * 36 + q * 4), src);
    }
#pragma unroll
    for (int t = 0; t < 4; ++t) {
        int id = tid + t * 256;
        int r = id >> 3, q = id & 7;
        cp_async16(smem_u32(B + r * 36 + q * 4), Bsrc + (n0 + r) * KTOT + k0 + q * 4);
    }
    cp_commit();
}

template <int MODE>
__global__ __launch_bounds__(256) void gemm_pipe(const float* __restrict__ bias,
                                                 float* __restrict__ Cext) {
    constexpr int NIT = (MODE == 0) ? 16 : (MODE == 1) ? 64 : 32;
    extern __shared__ float sm[];
    const int tid = threadIdx.x;
    const int warp = tid >> 5, lane = tid & 31;
    const int g = lane >> 2, tg = lane & 3;
    const int wm = (warp >> 1) * 32, wn = (warp & 1) * 64;
    const int m0 = blockIdx.y * 128, n0 = blockIdx.x * 128;
    const int kbase = (MODE == 0) ? blockIdx.z * 512 : 0;
    const float* Bsrc = (MODE == 0) ? g_cwT : (MODE == 1) ? g_gwT : g_owT;

    float acc[2][8][4];
#pragma unroll
    for (int mt = 0; mt < 2; ++mt)
#pragma unroll
        for (int j = 0; j < 8; ++j)
#pragma unroll
            for (int q = 0; q < 4; ++q) acc[mt][j][q] = 0.f;

    gp_load<MODE>(sm, 0, m0, n0, kbase, Bsrc, tid);

    for (int i = 0; i < NIT; ++i) {
        if (i + 1 < NIT) {
            gp_load<MODE>(sm, (i + 1) & 1, m0, n0, kbase + (i + 1) * 32, Bsrc, tid);
            asm volatile("cp.async.wait_group 1;" ::: "memory");
        } else {
            asm volatile("cp.async.wait_group 0;" ::: "memory");
        }
        __syncthreads();

        const float* As = sm + (i & 1) * STG_F;
        const float* Bs = As + 4608;
#pragma unroll
        for (int s = 0; s < 4; ++s) {
            const int ks = s * 8;
            uint32_t bf[8][2];
#pragma unroll
            for (int j = 0; j < 8; ++j) {
                int n = wn + j * 8 + g;
                bf[j][0] = __float_as_uint(Bs[n * 36 + ks + tg]);
                bf[j][1] = __float_as_uint(Bs[n * 36 + ks + tg + 4]);
            }
#pragma unroll
            for (int mt = 0; mt < 2; ++mt) {
                int r0 = wm + mt * 16 + g;
                uint32_t a0 = __float_as_uint(As[r0 * 36 + ks + tg]);
                uint32_t a1 = __float_as_uint(As[(r0 + 8) * 36 + ks + tg]);
                uint32_t a2 = __float_as_uint(As[r0 * 36 + ks + tg + 4]);
                uint32_t a3 = __float_as_uint(As[(r0 + 8) * 36 + ks + tg + 4]);
#pragma unroll
                for (int j = 0; j < 8; ++j)
                    mma_tf32(acc[mt][j], a0, a1, a2, a3, bf[j][0], bf[j][1]);
            }
        }
        __syncthreads();
    }

    // ---- epilogue ----
#pragma unroll
    for (int mt = 0; mt < 2; ++mt) {
#pragma unroll
        for (int j = 0; j < 8; ++j) {
            int col = n0 + wn + j * 8 + 2 * tg;
            int ra = m0 + wm + mt * 16 + g;
            int rb = ra + 8;
            if (MODE == 0) {
                atomicAdd(&g_comp[ra * 1024 + col], acc[mt][j][0]);
                atomicAdd(&g_comp[ra * 1024 + col + 1], acc[mt][j][1]);
                atomicAdd(&g_comp[rb * 1024 + col], acc[mt][j][2]);
                atomicAdd(&g_comp[rb * 1024 + col + 1], acc[mt][j][3]);
                continue;
            }
            float2 bz = *(const float2*)&bias[col];
            float z0x = acc[mt][j][0] + bz.x, z0y = acc[mt][j][1] + bz.y;
            float z1x = acc[mt][j][2] + bz.x, z1y = acc[mt][j][3] + bz.y;
            if (MODE == 1) {
                int ia = ra * 1024 + col, ib = rb * 1024 + col;
                float2 la = *(const float2*)&g_local[ia];
                float2 lb = *(const float2*)&g_local[ib];
                float2 ga = *(const float2*)&g_glob[ia];
                float2 gb = *(const float2*)&g_glob[ib];
                float s0x = 1.0f / (1.0f + fexp(-z0x));
                float s0y = 1.0f / (1.0f + fexp(-z0y));
                float s1x = 1.0f / (1.0f + fexp(-z1x));
                float s1y = 1.0f / (1.0f + fexp(-z1y));
                *(float2*)&g_mixed[ia] =
                    make_float2(rnd_tf32(s0x * la.x + (1.f - s0x) * ga.x),
                                rnd_tf32(s0y * la.y + (1.f - s0y) * ga.y));
                *(float2*)&g_mixed[ib] =
                    make_float2(rnd_tf32(s1x * lb.x + (1.f - s1x) * gb.x),
                                rnd_tf32(s1y * lb.y + (1.f - s1y) * gb.y));
            } else {
                *(float2*)&Cext[ra * 1024 + col] = make_float2(z0x, z0y);
                *(float2*)&Cext[rb * 1024 + col] = make_float2(z1x, z1y);
            }
        }
    }
}

// ---------------- launch ----------------
extern "C" void kernel_launch(void* const* d_in, const int* in_sizes, int n_in,
                              void* d_out, int out_size) {
    const float* x = (const float*)d_in[0];
    const float* pe = (const float*)d_in[1];
    const float* gm = (const float*)d_in[2];
    const float* cw = (const float*)d_in[3];
    const float* cb = (const float*)d_in[4];
    const float* gw = (const float*)d_in[5];
    const float* gb = (const float*)d_in[6];
    const float* ow = (const float*)d_in[7];
    const float* ob = (const float*)d_in[8];
    float* out = (float*)d_out;

    cudaFuncSetAttribute((const void*)local_attn_kernel,
                         cudaFuncAttributeMaxDynamicSharedMemorySize, 69632);
    cudaFuncSetAttribute((const void*)global_attn_kernel,
                         cudaFuncAttributeMaxDynamicSharedMemorySize, 69632);
    cudaFuncSetAttribute((const void*)gemm_pipe<0>,
                         cudaFuncAttributeMaxDynamicSharedMemorySize, GP_SMEM);
    cudaFuncSetAttribute((const void*)gemm_pipe<1>,
                         cudaFuncAttributeMaxDynamicSharedMemorySize, GP_SMEM);
    cudaFuncSetAttribute((const void*)gemm_pipe<2>,
                         cudaFuncAttributeMaxDynamicSharedMemorySize, GP_SMEM);

    float* gwT;
    float* owT;
    cudaGetSymbolAddress((void**)&gwT, g_gwT);
    cudaGetSymbolAddress((void**)&owT, g_owT);

    add_pos_kernel<<<16384, 256>>>(x, pe);
    transpose_kernel<<<dim3(32, 64), 256>>>(gw, gwT, 2048, 1024);
    transpose_kernel<<<dim3(32, 32), 256>>>(ow, owT, 1024, 1024);
    im2col_kernel<<<1024, 256>>>();
    cw_rearrange_kernel<<<4096, 256>>>(cw);
    zero_comp_kernel<<<256, 256>>>();
    gemm_pipe<0><<<dim3(8, 2, 8), 256, GP_SMEM>>>(nullptr, nullptr);  // conv split-K
    conv_scatter_kernel<<<256, 256>>>(cb);
    gt_fill_kernel<<<256, 256>>>(gm);
    local_attn_kernel<<<4096, 256, 69632>>>();
    global_attn_kernel<<<4096, 256, 69632>>>();
    gemm_pipe<1><<<dim3(8, 128), 256, GP_SMEM>>>(gb, nullptr);  // gate + mix
    gemm_pipe<2><<<dim3(8, 128), 256, GP_SMEM>>>(ob, out);      // output projection
}

// round 6
// speedup vs baseline: 3.6357x; 1.6848x over previous
#include <cuda_runtime.h>
#include <cstdint>

#define NB 4
#define SEQ 4096
#define DIM 1024
#define NH 16
#define HDIM 64
#define WINS 512
#define NWIN 8
#define NGT 128

// ---------------- scratch (static device globals; no allocation) ----------------
__device__ float g_xpos[NB * SEQ * DIM];   // x + pos_emb
__device__ float g_local[NB * SEQ * DIM];  // local attention out (tf32-rounded)
__device__ float g_glob[NB * SEQ * DIM];   // global attention out (tf32-rounded)
__device__ float g_mixed[NB * SEQ * DIM];  // gated mix (tf32-rounded)
__device__ float g_gt[NB * NGT * DIM];     // [comp ; global_memory] per batch
__device__ float g_gwT[DIM * 2 * DIM];     // gate_w transposed [1024][2048] (tf32)
__device__ float g_owT[DIM * DIM];         // out_w transposed  [1024][1024] (tf32)
__device__ float g_convA[256 * 4096];      // im2col A (tf32-rounded)
__device__ float g_cwT[DIM * 4096];        // conv_w rearranged [dout][ktap*1024+din]
__device__ float g_comp[256 * DIM];        // conv split-K accumulator

// ---------------- helpers ----------------
__device__ __forceinline__ uint32_t f2tf32(float x) {
    uint32_t r;
    asm("cvt.rna.tf32.f32 %0, %1;" : "=r"(r) : "f"(x));
    return r;
}
__device__ __forceinline__ float rnd_tf32(float x) {
    return __uint_as_float(f2tf32(x));
}
__device__ __forceinline__ uint32_t smem_u32(const void* p) {
    uint32_t a;
    asm("{ .reg .u64 t; cvta.to.shared.u64 t, %1; cvt.u32.u64 %0, t; }"
        : "=r"(a) : "l"(p));
    return a;
}
__device__ __forceinline__ void cp_async16(uint32_t dst, const float* src) {
    asm volatile("cp.async.cg.shared.global [%0], [%1], 16;"
                 :: "r"(dst), "l"(__cvta_generic_to_global(src)) : "memory");
}
__device__ __forceinline__ void cp_commit() {
    asm volatile("cp.async.commit_group;" ::: "memory");
}

// fast exp on fma/alu pipes (no MUFU). |rel err| ~2e-6 for x <= 0.
__device__ __forceinline__ float fexp(float x) {
    float z = fmaxf(x, -87.3365f) * 1.4426950408889634f;
    float s = z + 12582912.0f;
    int n = __float_as_int(s) - 0x4b400000;
    float f = z - (s - 12582912.0f);
    float p = 1.3371542e-3f;
    p = fmaf(p, f, 9.6181291e-3f);
    p = fmaf(p, f, 5.5504109e-2f);
    p = fmaf(p, f, 2.4022651e-1f);
    p = fmaf(p, f, 6.9314718e-1f);
    p = fmaf(p, f, 1.0f);
    return __int_as_float(__float_as_int(p) + (n << 23));
}

__device__ __forceinline__ void mma_tf32(float* c, uint32_t a0, uint32_t a1,
                                         uint32_t a2, uint32_t a3,
                                         uint32_t b0, uint32_t b1) {
    asm volatile(
        "mma.sync.aligned.m16n8k8.row.col.f32.tf32.tf32.f32 "
        "{%0,%1,%2,%3}, {%4,%5,%6,%7}, {%8,%9}, {%0,%1,%2,%3};"
        : "+f"(c[0]), "+f"(c[1]), "+f"(c[2]), "+f"(c[3])
        : "r"(a0), "r"(a1), "r"(a2), "r"(a3), "r"(b0), "r"(b1));
}

// ---------------- kernel: x + pos_emb ----------------
__global__ __launch_bounds__(256) void add_pos_kernel(const float* __restrict__ x,
                                                      const float* __restrict__ pe) {
    int i = blockIdx.x * 256 + threadIdx.x;
    float4 a = ((const float4*)x)[i];
    float4 p = ((const float4*)pe)[i & 1048575];
    float4 r;
    r.x = a.x + p.x; r.y = a.y + p.y; r.z = a.z + p.z; r.w = a.w + p.w;
    ((float4*)g_xpos)[i] = r;
}

// ---------------- fill global_memory half of gt ----------------
__global__ __launch_bounds__(256) void gt_fill_kernel(const float* __restrict__ gm) {
    int i = blockIdx.x * 256 + threadIdx.x;
    float4 v = ((const float4*)gm)[i & 16383];
    ((float4*)g_gt)[(i >> 14) * 32768 + 16384 + (i & 16383)] = v;
}

// ---------------- transpose + tf32 round: in[K][N] -> out[N][K] ----------------
__global__ __launch_bounds__(256) void transpose_kernel(const float* __restrict__ in,
                                                        float* __restrict__ out,
                                                        int K, int N) {
    __shared__ float t[32][33];
    int bx = blockIdx.x * 32;
    int by = blockIdx.y * 32;
    int x = threadIdx.x & 31, y = threadIdx.x >> 5;
#pragma unroll
    for (int i = 0; i < 32; i += 8) t[y + i][x] = in[(by + y + i) * N + bx + x];
    __syncthreads();
#pragma unroll
    for (int i = 0; i < 32; i += 8)
        out[(bx + y + i) * K + by + x] = rnd_tf32(t[x][y + i]);
}

// ---------------- conv pre-transforms ----------------
__global__ __launch_bounds__(256) void im2col_kernel() {
    int i = blockIdx.x * 256 + threadIdx.x;
    int r = i >> 10, q = i & 1023;
    int c4 = q << 2;
    int ktap = c4 >> 10, din = c4 & 1023;
    int b = r >> 6, g = r & 63;
    float4 v = *(const float4*)(g_xpos + ((b << 12) + (g << 2) + ktap) * DIM + din);
    float4 o;
    o.x = rnd_tf32(v.x); o.y = rnd_tf32(v.y); o.z = rnd_tf32(v.z); o.w = rnd_tf32(v.w);
    *(float4*)(g_convA + r * 4096 + c4) = o;
}

__global__ __launch_bounds__(256) void cw_rearrange_kernel(const float* __restrict__ cw) {
    int i = blockIdx.x * 256 + threadIdx.x;
    int dout = i >> 10, q = i & 1023;
    int c4 = q << 2;
    int ktap = c4 >> 10, din = c4 & 1023;
    const float* base = cw + dout * 4096 + din * 4 + ktap;
    float4 o;
    o.x = rnd_tf32(base[0]);
    o.y = rnd_tf32(base[4]);
    o.z = rnd_tf32(base[8]);
    o.w = rnd_tf32(base[12]);
    *(float4*)(g_cwT + dout * 4096 + c4) = o;
}

__global__ __launch_bounds__(256) void zero_comp_kernel() {
    int i = blockIdx.x * 256 + threadIdx.x;
    ((float4*)g_comp)[i] = make_float4(0.f, 0.f, 0.f, 0.f);
}

__global__ __launch_bounds__(256) void conv_scatter_kernel(const float* __restrict__ cb) {
    int i = blockIdx.x * 256 + threadIdx.x;
    int r = i >> 8, c4 = (i & 255) << 2;
    float4 v = *(const float4*)(g_comp + r * 1024 + c4);
    float4 b = *(const float4*)(cb + c4);
    v.x += b.x; v.y += b.y; v.z += b.z; v.w += b.w;
    int outr = ((r >> 6) << 7) | (r & 63);
    *(float4*)(g_gt + outr * 1024 + c4) = v;
}

// ================= tensor-core flash attention (128 q-rows, 8 warps) =================
// smem: Ks[64][68] (K row-major, tf32), Vt[64][68] (V transposed, tf32),
//       Ps[128][68] (Q staging, then P scratch)
// Warp w owns q-rows [16w, 16w+16): full-width rows -> softmax stats are quad-local.
__device__ __forceinline__ void flash_mma(const float* __restrict__ qb,
                                          const float* __restrict__ kb,
                                          float* __restrict__ obp, int nkt) {
    extern __shared__ float sm[];
    float* Ks = sm;           // 4352 floats
    float* Vt = sm + 4352;    // 4352 floats
    float* Ps = sm + 8704;    // 8704 floats
    const int tid = threadIdx.x;
    const int warp = tid >> 5, lane = tid & 31;
    const int g = lane >> 2, tg = lane & 3;
    const int wm = warp * 16;

    // stage Q (scaled by 1/8, tf32-rounded) into Ps
#pragma unroll
    for (int it = 0; it < 8; ++it) {
        int f = tid + it * 256;               // 2048 float4 slots: 128 rows x 16
        int row = f >> 4, c4 = (f & 15) << 2;
        float4 v = *(const float4*)(qb + row * DIM + c4);
        float* d = Ps + row * 68 + c4;
        d[0] = rnd_tf32(v.x * 0.125f);
        d[1] = rnd_tf32(v.y * 0.125f);
        d[2] = rnd_tf32(v.z * 0.125f);
        d[3] = rnd_tf32(v.w * 0.125f);
    }
    __syncthreads();

    // Q fragments (register-resident across all k-tiles)
    uint32_t qf[8][4];
#pragma unroll
    for (int ks = 0; ks < 8; ++ks) {
        qf[ks][0] = __float_as_uint(Ps[(wm + g) * 68 + ks * 8 + tg]);
        qf[ks][1] = __float_as_uint(Ps[(wm + g + 8) * 68 + ks * 8 + tg]);
        qf[ks][2] = __float_as_uint(Ps[(wm + g) * 68 + ks * 8 + tg + 4]);
        qf[ks][3] = __float_as_uint(Ps[(wm + g + 8) * 68 + ks * 8 + tg + 4]);
    }

    float m0 = -1e30f, m1 = -1e30f, l0 = 0.f, l1 = 0.f;
    float oacc[8][4];
#pragma unroll
    for (int j = 0; j < 8; ++j)
#pragma unroll
        for (int q = 0; q < 4; ++q) oacc[j][q] = 0.f;

    for (int kt = 0; kt < nkt; ++kt) {
        __syncthreads();  // prev iter's Ks/Vt/Ps reads complete
        // load K(=V) tile: row-major into Ks, transposed into Vt (tf32-rounded)
#pragma unroll
        for (int it = 0; it < 4; ++it) {
            int f = tid + it * 256;           // 1024 float4 slots: 64 rows x 16
            int row = f >> 4, c4 = (f & 15) << 2;
            float4 v = *(const float4*)(kb + (kt * 64 + row) * DIM + c4);
            float x0 = rnd_tf32(v.x), x1 = rnd_tf32(v.y);
            float x2 = rnd_tf32(v.z), x3 = rnd_tf32(v.w);
            *(float4*)(Ks + row * 68 + c4) = make_float4(x0, x1, x2, x3);
            Vt[(c4 + 0) * 68 + row] = x0;
            Vt[(c4 + 1) * 68 + row] = x1;
            Vt[(c4 + 2) * 68 + row] = x2;
            Vt[(c4 + 3) * 68 + row] = x3;
        }
        __syncthreads();

        // S = Q K^T : 8 n-frags x 8 k-steps
        float sacc[8][4];
#pragma unroll
        for (int j = 0; j < 8; ++j)
#pragma unroll
            for (int q = 0; q < 4; ++q) sacc[j][q] = 0.f;
#pragma unroll
        for (int ks = 0; ks < 8; ++ks) {
#pragma unroll
            for (int j = 0; j < 8; ++j) {
                uint32_t b0 = __float_as_uint(Ks[(j * 8 + g) * 68 + ks * 8 + tg]);
                uint32_t b1 = __float_as_uint(Ks[(j * 8 + g) * 68 + ks * 8 + tg + 4]);
                mma_tf32(sacc[j], qf[ks][0], qf[ks][1], qf[ks][2], qf[ks][3], b0, b1);
            }
        }

        // online softmax; rows r0=wm+g (c0,c1), r1=wm+g+8 (c2,c3)
        float mx0 = -1e30f, mx1 = -1e30f;
#pragma unroll
        for (int j = 0; j < 8; ++j) {
            mx0 = fmaxf(mx0, fmaxf(sacc[j][0], sacc[j][1]));
            mx1 = fmaxf(mx1, fmaxf(sacc[j][2], sacc[j][3]));
        }
        mx0 = fmaxf(mx0, __shfl_xor_sync(0xffffffffu, mx0, 1));
        mx0 = fmaxf(mx0, __shfl_xor_sync(0xffffffffu, mx0, 2));
        mx1 = fmaxf(mx1, __shfl_xor_sync(0xffffffffu, mx1, 1));
        mx1 = fmaxf(mx1, __shfl_xor_sync(0xffffffffu, mx1, 2));
        float mn0 = fmaxf(m0, mx0), mn1 = fmaxf(m1, mx1);
        float c0 = fexp(m0 - mn0), c1 = fexp(m1 - mn1);
        m0 = mn0; m1 = mn1;
        float s0 = 0.f, s1 = 0.f;
#pragma unroll
        for (int j = 0; j < 8; ++j) {
            sacc[j][0] = fexp(sacc[j][0] - mn0);
            sacc[j][1] = fexp(sacc[j][1] - mn0);
            sacc[j][2] = fexp(sacc[j][2] - mn1);
            sacc[j][3] = fexp(sacc[j][3] - mn1);
            s0 += sacc[j][0] + sacc[j][1];
            s1 += sacc[j][2] + sacc[j][3];
        }
        s0 += __shfl_xor_sync(0xffffffffu, s0, 1);
        s0 += __shfl_xor_sync(0xffffffffu, s0, 2);
        s1 += __shfl_xor_sync(0xffffffffu, s1, 1);
        s1 += __shfl_xor_sync(0xffffffffu, s1, 2);
        l0 = l0 * c0 + s0;
        l1 = l1 * c1 + s1;
#pragma unroll
        for (int j = 0; j < 8; ++j) {
            oacc[j][0] *= c0; oacc[j][1] *= c0;
            oacc[j][2] *= c1; oacc[j][3] *= c1;
        }

        // write P (tf32) to warp-private rows of Ps; reload as A fragments
#pragma unroll
        for (int j = 0; j < 8; ++j) {
            int cb = j * 8 + 2 * tg;
            Ps[(wm + g) * 68 + cb] = rnd_tf32(sacc[j][0]);
            Ps[(wm + g) * 68 + cb + 1] = rnd_tf32(sacc[j][1]);
            Ps[(wm + g + 8) * 68 + cb] = rnd_tf32(sacc[j][2]);
            Ps[(wm + g + 8) * 68 + cb + 1] = rnd_tf32(sacc[j][3]);
        }
        __syncwarp();

        // O += P V  (B operand from Vt[d][key])
#pragma unroll
        for (int ks = 0; ks < 8; ++ks) {
            uint32_t a0 = __float_as_uint(Ps[(wm + g) * 68 + ks * 8 + tg]);
            uint32_t a1 = __float_as_uint(Ps[(wm + g + 8) * 68 + ks * 8 + tg]);
            uint32_t a2 = __float_as_uint(Ps[(wm + g) * 68 + ks * 8 + tg + 4]);
            uint32_t a3 = __float_as_uint(Ps[(wm + g + 8) * 68 + ks * 8 + tg + 4]);
#pragma unroll
            for (int j = 0; j < 8; ++j) {
                uint32_t b0 = __float_as_uint(Vt[(j * 8 + g) * 68 + ks * 8 + tg]);
                uint32_t b1 = __float_as_uint(Vt[(j * 8 + g) * 68 + ks * 8 + tg + 4]);
                mma_tf32(oacc[j], a0, a1, a2, a3, b0, b1);
            }
        }
    }

    // normalize + store (tf32-rounded: feeds downstream GEMM A)
    float inv0 = 1.0f / l0, inv1 = 1.0f / l1;
#pragma unroll
    for (int j = 0; j < 8; ++j) {
        int cb = j * 8 + 2 * tg;
        *(float2*)(obp + (wm + g) * DIM + cb) =
            make_float2(rnd_tf32(oacc[j][0] * inv0), rnd_tf32(oacc[j][1] * inv0));
        *(float2*)(obp + (wm + g + 8) * DIM + cb) =
            make_float2(rnd_tf32(oacc[j][2] * inv1), rnd_tf32(oacc[j][3] * inv1));
    }
}

// local: 2048 blocks = b(2) | w(3) | h(4) | qt(2)
__global__ __launch_bounds__(256, 2) void local_attn_kernel() {
    int bx = blockIdx.x;
    int qt = bx & 3;
    int h = (bx >> 2) & 15;
    int w = (bx >> 6) & 7;
    int b = bx >> 9;
    const float* base = g_xpos + (b * SEQ + w * WINS) * DIM + h * HDIM;
    const float* qb = base + (qt * 128) * DIM;
    float* ob = g_local + (b * SEQ + w * WINS + qt * 128) * DIM + h * HDIM;
    flash_mma(qb, base, ob, 8);
}

// global: 2048 blocks = b(2) | h(4) | qt(5)
__global__ __launch_bounds__(256, 2) void global_attn_kernel() {
    int bx = blockIdx.x;
    int qt = bx & 31;
    int h = (bx >> 5) & 15;
    int b = bx >> 9;
    const float* qb = g_xpos + (b * SEQ + qt * 128) * DIM + h * HDIM;
    const float* kb = g_gt + (b * NGT) * DIM + h * HDIM;
    float* ob = g_glob + (b * SEQ + qt * 128) * DIM + h * HDIM;
    flash_mma(qb, kb, ob, 2);
}

// ==================== pipelined tf32 mma GEMM, 128x128 tile, KT=32 ====================
#define STG_F 9216
#define GP_SMEM (2 * STG_F * 4)

template <int MODE>
__device__ __forceinline__ void gp_load(float* sm, int s, int m0, int n0, int k0,
                                        const float* Bsrc, int tid) {
    float* A = sm + s * STG_F;
    float* B = A + 4608;
    constexpr int KTOT = (MODE == 0) ? 4096 : (MODE == 1) ? 2048 : 1024;
#pragma unroll
    for (int t = 0; t < 4; ++t) {
        int id = tid + t * 256;
        int r = id >> 3, q = id & 7;
        int kk = k0 + q * 4;
        const float* src;
        if (MODE == 0) {
            src = g_convA + (m0 + r) * 4096 + kk;
        } else if (MODE == 1) {
            src = (kk < 1024) ? g_local + (m0 + r) * 1024 + kk
                              : g_glob + (m0 + r) * 1024 + (kk - 1024);
        } else {
            src = g_mixed + (m0 + r) * 1024 + kk;
        }
        cp_async16(smem_u32(A + r * 36 + q * 4), src);
    }
#pragma unroll
    for (int t = 0; t < 4; ++t) {
        int id = tid + t * 256;
        int r = id >> 3, q = id & 7;
        cp_async16(smem_u32(B + r * 36 + q * 4), Bsrc + (n0 + r) * KTOT + k0 + q * 4);
    }
    cp_commit();
}

template <int MODE>
__global__ __launch_bounds__(256) void gemm_pipe(const float* __restrict__ bias,
                                                 float* __restrict__ Cext) {
    constexpr int NIT = (MODE == 0) ? 16 : (MODE == 1) ? 64 : 32;
    extern __shared__ float sm[];
    const int tid = threadIdx.x;
    const int warp = tid >> 5, lane = tid & 31;
    const int g = lane >> 2, tg = lane & 3;
    const int wm = (warp >> 1) * 32, wn = (warp & 1) * 64;
    const int m0 = blockIdx.y * 128, n0 = blockIdx.x * 128;
    const int kbase = (MODE == 0) ? blockIdx.z * 512 : 0;
    const float* Bsrc = (MODE == 0) ? g_cwT : (MODE == 1) ? g_gwT : g_owT;

    float acc[2][8][4];
#pragma unroll
    for (int mt = 0; mt < 2; ++mt)
#pragma unroll
        for (int j = 0; j < 8; ++j)
#pragma unroll
            for (int q = 0; q < 4; ++q) acc[mt][j][q] = 0.f;

    gp_load<MODE>(sm, 0, m0, n0, kbase, Bsrc, tid);

    for (int i = 0; i < NIT; ++i) {
        if (i + 1 < NIT) {
            gp_load<MODE>(sm, (i + 1) & 1, m0, n0, kbase + (i + 1) * 32, Bsrc, tid);
            asm volatile("cp.async.wait_group 1;" ::: "memory");
        } else {
            asm volatile("cp.async.wait_group 0;" ::: "memory");
        }
        __syncthreads();

        const float* As = sm + (i & 1) * STG_F;
        const float* Bs = As + 4608;
#pragma unroll
        for (int s = 0; s < 4; ++s) {
            const int ks = s * 8;
            uint32_t bf[8][2];
#pragma unroll
            for (int j = 0; j < 8; ++j) {
                int n = wn + j * 8 + g;
                bf[j][0] = __float_as_uint(Bs[n * 36 + ks + tg]);
                bf[j][1] = __float_as_uint(Bs[n * 36 + ks + tg + 4]);
            }
#pragma unroll
            for (int mt = 0; mt < 2; ++mt) {
                int r0 = wm + mt * 16 + g;
                uint32_t a0 = __float_as_uint(As[r0 * 36 + ks + tg]);
                uint32_t a1 = __float_as_uint(As[(r0 + 8) * 36 + ks + tg]);
                uint32_t a2 = __float_as_uint(As[r0 * 36 + ks + tg + 4]);
                uint32_t a3 = __float_as_uint(As[(r0 + 8) * 36 + ks + tg + 4]);
#pragma unroll
                for (int j = 0; j < 8; ++j)
                    mma_tf32(acc[mt][j], a0, a1, a2, a3, bf[j][0], bf[j][1]);
            }
        }
        __syncthreads();
    }

#pragma unroll
    for (int mt = 0; mt < 2; ++mt) {
#pragma unroll
        for (int j = 0; j < 8; ++j) {
            int col = n0 + wn + j * 8 + 2 * tg;
            int ra = m0 + wm + mt * 16 + g;
            int rb = ra + 8;
            if (MODE == 0) {
                atomicAdd(&g_comp[ra * 1024 + col], acc[mt][j][0]);
                atomicAdd(&g_comp[ra * 1024 + col + 1], acc[mt][j][1]);
                atomicAdd(&g_comp[rb * 1024 + col], acc[mt][j][2]);
                atomicAdd(&g_comp[rb * 1024 + col + 1], acc[mt][j][3]);
                continue;
            }
            float2 bz = *(const float2*)&bias[col];
            float z0x = acc[mt][j][0] + bz.x, z0y = acc[mt][j][1] + bz.y;
            float z1x = acc[mt][j][2] + bz.x, z1y = acc[mt][j][3] + bz.y;
            if (MODE == 1) {
                int ia = ra * 1024 + col, ib = rb * 1024 + col;
                float2 la = *(const float2*)&g_local[ia];
                float2 lb = *(const float2*)&g_local[ib];
                float2 ga = *(const float2*)&g_glob[ia];
                float2 gb = *(const float2*)&g_glob[ib];
                float s0x = 1.0f / (1.0f + fexp(-z0x));
                float s0y = 1.0f / (1.0f + fexp(-z0y));
                float s1x = 1.0f / (1.0f + fexp(-z1x));
                float s1y = 1.0f / (1.0f + fexp(-z1y));
                *(float2*)&g_mixed[ia] =
                    make_float2(rnd_tf32(s0x * la.x + (1.f - s0x) * ga.x),
                                rnd_tf32(s0y * la.y + (1.f - s0y) * ga.y));
                *(float2*)&g_mixed[ib] =
                    make_float2(rnd_tf32(s1x * lb.x + (1.f - s1x) * gb.x),
                                rnd_tf32(s1y * lb.y + (1.f - s1y) * gb.y));
            } else {
                *(float2*)&Cext[ra * 1024 + col] = make_float2(z0x, z0y);
                *(float2*)&Cext[rb * 1024 + col] = make_float2(z1x, z1y);
            }
        }
    }
}

// ---------------- launch ----------------
extern "C" void kernel_launch(void* const* d_in, const int* in_sizes, int n_in,
                              void* d_out, int out_size) {
    const float* x = (const float*)d_in[0];
    const float* pe = (const float*)d_in[1];
    const float* gm = (const float*)d_in[2];
    const float* cw = (const float*)d_in[3];
    const float* cb = (const float*)d_in[4];
    const float* gw = (const float*)d_in[5];
    const float* gb = (const float*)d_in[6];
    const float* ow = (const float*)d_in[7];
    const float* ob = (const float*)d_in[8];
    float* out = (float*)d_out;

    cudaFuncSetAttribute((const void*)local_attn_kernel,
                         cudaFuncAttributeMaxDynamicSharedMemorySize, 69632);
    cudaFuncSetAttribute((const void*)global_attn_kernel,
                         cudaFuncAttributeMaxDynamicSharedMemorySize, 69632);
    cudaFuncSetAttribute((const void*)gemm_pipe<0>,
                         cudaFuncAttributeMaxDynamicSharedMemorySize, GP_SMEM);
    cudaFuncSetAttribute((const void*)gemm_pipe<1>,
                         cudaFuncAttributeMaxDynamicSharedMemorySize, GP_SMEM);
    cudaFuncSetAttribute((const void*)gemm_pipe<2>,
                         cudaFuncAttributeMaxDynamicSharedMemorySize, GP_SMEM);

    add_pos_kernel<<<16384, 256>>>(x, pe);
    {
        float* gwT; float* owT;
        cudaGetSymbolAddress((void**)&gwT, g_gwT);
        cudaGetSymbolAddress((void**)&owT, g_owT);
        transpose_kernel<<<dim3(32, 64), 256>>>(gw, gwT, 2048, 1024);
        transpose_kernel<<<dim3(32, 32), 256>>>(ow, owT, 1024, 1024);
    }
    im2col_kernel<<<1024, 256>>>();
    cw_rearrange_kernel<<<4096, 256>>>(cw);
    zero_comp_kernel<<<256, 256>>>();
    gemm_pipe<0><<<dim3(8, 2, 8), 256, GP_SMEM>>>(nullptr, nullptr);  // conv split-K
    conv_scatter_kernel<<<256, 256>>>(cb);
    gt_fill_kernel<<<256, 256>>>(gm);
    local_attn_kernel<<<2048, 256, 69632>>>();
    global_attn_kernel<<<2048, 256, 69632>>>();
    gemm_pipe<1><<<dim3(8, 128), 256, GP_SMEM>>>(gb, nullptr);  // gate + mix
    gemm_pipe<2><<<dim3(8, 128), 256, GP_SMEM>>>(ob, out);      // output projection
}

// round 7
// speedup vs baseline: 5.6676x; 1.5589x over previous
#include <cuda_runtime.h>
#include <cuda_fp16.h>
#include <cstdint>

#define NB 4
#define SEQ 4096
#define DIM 1024
#define NH 16
#define HDIM 64
#define WINS 512
#define NWIN 8
#define NGT 128

// ---------------- scratch (static device globals; no allocation) ----------------
__device__ float g_xpos[NB * SEQ * DIM];     // x + pos_emb (fp32)
__device__ __half g_local[NB * SEQ * DIM];   // local attention out
__device__ __half g_glob[NB * SEQ * DIM];    // global attention out
__device__ __half g_mixed[NB * SEQ * DIM];   // gated mix
__device__ float g_gt[NB * NGT * DIM];       // [comp ; global_memory] per batch (fp32)
__device__ __half g_gwT[DIM * 2 * DIM];      // gate_w transposed [1024][2048]
__device__ __half g_owT[DIM * DIM];          // out_w transposed  [1024][1024]
__device__ __half g_convA[256 * 4096];       // im2col A
__device__ __half g_cwT[DIM * 4096];         // conv_w rearranged [dout][ktap*1024+din]
__device__ float g_comp[256 * DIM];          // conv split-K accumulator (fp32)

// ---------------- helpers ----------------
__device__ __forceinline__ uint32_t pack2(float a, float b) {
    __half2 h = __floats2half2_rn(a, b);
    return *(uint32_t*)&h;
}
__device__ __forceinline__ uint32_t smem_u32(const void* p) {
    uint32_t a;
    asm("{ .reg .u64 t; cvta.to.shared.u64 t, %1; cvt.u32.u64 %0, t; }"
        : "=r"(a) : "l"(p));
    return a;
}
__device__ __forceinline__ void cp_async16(uint32_t dst, const void* src) {
    asm volatile("cp.async.cg.shared.global [%0], [%1], 16;"
                 :: "r"(dst), "l"(__cvta_generic_to_global(src)) : "memory");
}
__device__ __forceinline__ void cp_commit() {
    asm volatile("cp.async.commit_group;" ::: "memory");
}

// fast exp on fma/alu pipes (no MUFU). |rel err| ~2e-6 for x <= 0.
__device__ __forceinline__ float fexp(float x) {
    float z = fmaxf(x, -87.3365f) * 1.4426950408889634f;
    float s = z + 12582912.0f;
    int n = __float_as_int(s) - 0x4b400000;
    float f = z - (s - 12582912.0f);
    float p = 1.3371542e-3f;
    p = fmaf(p, f, 9.6181291e-3f);
    p = fmaf(p, f, 5.5504109e-2f);
    p = fmaf(p, f, 2.4022651e-1f);
    p = fmaf(p, f, 6.9314718e-1f);
    p = fmaf(p, f, 1.0f);
    return __int_as_float(__float_as_int(p) + (n << 23));
}

// fp16 mma with fp32 accum: D = A(16x16) B(16x8) + D
__device__ __forceinline__ void mma_f16(float* c, uint32_t a0, uint32_t a1,
                                        uint32_t a2, uint32_t a3,
                                        uint32_t b0, uint32_t b1) {
    asm volatile(
        "mma.sync.aligned.m16n8k16.row.col.f32.f16.f16.f32 "
        "{%0,%1,%2,%3}, {%4,%5,%6,%7}, {%8,%9}, {%0,%1,%2,%3};"
        : "+f"(c[0]), "+f"(c[1]), "+f"(c[2]), "+f"(c[3])
        : "r"(a0), "r"(a1), "r"(a2), "r"(a3), "r"(b0), "r"(b1));
}

#define LDH32(arr, idx) (*(const uint32_t*)((arr) + (idx)))

// ---------------- kernel: x + pos_emb ----------------
__global__ __launch_bounds__(256) void add_pos_kernel(const float* __restrict__ x,
                                                      const float* __restrict__ pe) {
    int i = blockIdx.x * 256 + threadIdx.x;
    float4 a = ((const float4*)x)[i];
    float4 p = ((const float4*)pe)[i & 1048575];
    float4 r;
    r.x = a.x + p.x; r.y = a.y + p.y; r.z = a.z + p.z; r.w = a.w + p.w;
    ((float4*)g_xpos)[i] = r;
}

// ---------------- fill global_memory half of gt ----------------
__global__ __launch_bounds__(256) void gt_fill_kernel(const float* __restrict__ gm) {
    int i = blockIdx.x * 256 + threadIdx.x;
    float4 v = ((const float4*)gm)[i & 16383];
    ((float4*)g_gt)[(i >> 14) * 32768 + 16384 + (i & 16383)] = v;
}

// ---------------- transpose + fp16: in[K][N] -> out[N][K] ----------------
__global__ __launch_bounds__(256) void transpose_kernel(const float* __restrict__ in,
                                                        __half* __restrict__ out,
                                                        int K, int N) {
    __shared__ float t[32][33];
    int bx = blockIdx.x * 32;
    int by = blockIdx.y * 32;
    int x = threadIdx.x & 31, y = threadIdx.x >> 5;
#pragma unroll
    for (int i = 0; i < 32; i += 8) t[y + i][x] = in[(by + y + i) * N + bx + x];
    __syncthreads();
#pragma unroll
    for (int i = 0; i < 32; i += 8)
        out[(bx + y + i) * K + by + x] = __float2half_rn(t[x][y + i]);
}

// ---------------- conv pre-transforms ----------------
__global__ __launch_bounds__(256) void im2col_kernel() {
    int i = blockIdx.x * 256 + threadIdx.x;  // 262144 4-elem groups
    int r = i >> 10, q = i & 1023;
    int c4 = q << 2;
    int ktap = c4 >> 10, din = c4 & 1023;
    int b = r >> 6, g = r & 63;
    float4 v = *(const float4*)(g_xpos + ((b << 12) + (g << 2) + ktap) * DIM + din);
    *(uint2*)(g_convA + r * 4096 + c4) =
        make_uint2(pack2(v.x, v.y), pack2(v.z, v.w));
}

__global__ __launch_bounds__(256) void cw_rearrange_kernel(const float* __restrict__ cw) {
    int i = blockIdx.x * 256 + threadIdx.x;  // 1048576 4-elem groups
    int dout = i >> 10, q = i & 1023;
    int c4 = q << 2;
    int ktap = c4 >> 10, din = c4 & 1023;
    const float* base = cw + dout * 4096 + din * 4 + ktap;
    *(uint2*)(g_cwT + dout * 4096 + c4) =
        make_uint2(pack2(base[0], base[4]), pack2(base[8], base[12]));
}

__global__ __launch_bounds__(256) void zero_comp_kernel() {
    int i = blockIdx.x * 256 + threadIdx.x;
    ((float4*)g_comp)[i] = make_float4(0.f, 0.f, 0.f, 0.f);
}

__global__ __launch_bounds__(256) void conv_scatter_kernel(const float* __restrict__ cb) {
    int i = blockIdx.x * 256 + threadIdx.x;
    int r = i >> 8, c4 = (i & 255) << 2;
    float4 v = *(const float4*)(g_comp + r * 1024 + c4);
    float4 b = *(const float4*)(cb + c4);
    v.x += b.x; v.y += b.y; v.z += b.z; v.w += b.w;
    int outr = ((r >> 6) << 7) | (r & 63);
    *(float4*)(g_gt + outr * 1024 + c4) = v;
}

// ============= fp16 tensor-core flash attention (128 q-rows, 8 warps) =============
// smem (halves): Ks[64][72] (K row-major), Vt[64][72] (V transposed: [d][key]),
//                Ps[128][72] (Q staging, then P scratch). 36864 bytes.
__device__ __forceinline__ void flash_mma(const float* __restrict__ qb,
                                          const float* __restrict__ kb,
                                          __half* __restrict__ obp, int nkt) {
    extern __shared__ __half smh[];
    __half* Ks = smh;            // 4608 halves
    __half* Vt = smh + 4608;     // 4608 halves
    __half* Ps = smh + 9216;     // 9216 halves
    const int tid = threadIdx.x;
    const int warp = tid >> 5, lane = tid & 31;
    const int g = lane >> 2, tg = lane & 3;
    const int wm = warp * 16;

    // stage Q (scaled by 1/8) into Ps as fp16
#pragma unroll
    for (int it = 0; it < 8; ++it) {
        int f = tid + it * 256;               // 2048 slots: 128 rows x 16
        int row = f >> 4, c4 = (f & 15) << 2;
        float4 v = *(const float4*)(qb + row * DIM + c4);
        *(uint2*)(Ps + row * 72 + c4) =
            make_uint2(pack2(v.x * 0.125f, v.y * 0.125f),
                       pack2(v.z * 0.125f, v.w * 0.125f));
    }
    __syncthreads();

    // Q fragments (register-resident), 4 k-steps of 16
    uint32_t qf[4][4];
#pragma unroll
    for (int ks = 0; ks < 4; ++ks) {
        qf[ks][0] = LDH32(Ps, (wm + g) * 72 + ks * 16 + 2 * tg);
        qf[ks][1] = LDH32(Ps, (wm + g + 8) * 72 + ks * 16 + 2 * tg);
        qf[ks][2] = LDH32(Ps, (wm + g) * 72 + ks * 16 + 2 * tg + 8);
        qf[ks][3] = LDH32(Ps, (wm + g + 8) * 72 + ks * 16 + 2 * tg + 8);
    }

    float m0 = -1e30f, m1 = -1e30f, l0 = 0.f, l1 = 0.f;
    float oacc[8][4];
#pragma unroll
    for (int j = 0; j < 8; ++j)
#pragma unroll
        for (int q = 0; q < 4; ++q) oacc[j][q] = 0.f;

    for (int kt = 0; kt < nkt; ++kt) {
        __syncthreads();
        // K(=V) tile: row-major Ks + transposed Vt, fp16
#pragma unroll
        for (int it = 0; it < 4; ++it) {
            int f = tid + it * 256;           // 1024 slots: 64 rows x 16
            int row = f >> 4, c4 = (f & 15) << 2;
            float4 v = *(const float4*)(kb + (kt * 64 + row) * DIM + c4);
            __half h0 = __float2half_rn(v.x), h1 = __float2half_rn(v.y);
            __half h2 = __float2half_rn(v.z), h3 = __float2half_rn(v.w);
            __half2 p01; p01.x = h0; p01.y = h1;
            __half2 p23; p23.x = h2; p23.y = h3;
            *(uint2*)(Ks + row * 72 + c4) =
                make_uint2(*(uint32_t*)&p01, *(uint32_t*)&p23);
            Vt[(c4 + 0) * 72 + row] = h0;
            Vt[(c4 + 1) * 72 + row] = h1;
            Vt[(c4 + 2) * 72 + row] = h2;
            Vt[(c4 + 3) * 72 + row] = h3;
        }
        __syncthreads();

        // S = Q K^T
        float sacc[8][4];
#pragma unroll
        for (int j = 0; j < 8; ++j)
#pragma unroll
            for (int q = 0; q < 4; ++q) sacc[j][q] = 0.f;
#pragma unroll
        for (int ks = 0; ks < 4; ++ks) {
#pragma unroll
            for (int j = 0; j < 8; ++j) {
                uint32_t b0 = LDH32(Ks, (j * 8 + g) * 72 + ks * 16 + 2 * tg);
                uint32_t b1 = LDH32(Ks, (j * 8 + g) * 72 + ks * 16 + 2 * tg + 8);
                mma_f16(sacc[j], qf[ks][0], qf[ks][1], qf[ks][2], qf[ks][3], b0, b1);
            }
        }

        // online softmax; rows r0=wm+g, r1=wm+g+8 (quad-local reductions)
        float mx0 = -1e30f, mx1 = -1e30f;
#pragma unroll
        for (int j = 0; j < 8; ++j) {
            mx0 = fmaxf(mx0, fmaxf(sacc[j][0], sacc[j][1]));
            mx1 = fmaxf(mx1, fmaxf(sacc[j][2], sacc[j][3]));
        }
        mx0 = fmaxf(mx0, __shfl_xor_sync(0xffffffffu, mx0, 1));
        mx0 = fmaxf(mx0, __shfl_xor_sync(0xffffffffu, mx0, 2));
        mx1 = fmaxf(mx1, __shfl_xor_sync(0xffffffffu, mx1, 1));
        mx1 = fmaxf(mx1, __shfl_xor_sync(0xffffffffu, mx1, 2));
        float mn0 = fmaxf(m0, mx0), mn1 = fmaxf(m1, mx1);
        float c0 = fexp(m0 - mn0), c1 = fexp(m1 - mn1);
        m0 = mn0; m1 = mn1;
        float s0 = 0.f, s1 = 0.f;
#pragma unroll
        for (int j = 0; j < 8; ++j) {
            sacc[j][0] = fexp(sacc[j][0] - mn0);
            sacc[j][1] = fexp(sacc[j][1] - mn0);
            sacc[j][2] = fexp(sacc[j][2] - mn1);
            sacc[j][3] = fexp(sacc[j][3] - mn1);
            s0 += sacc[j][0] + sacc[j][1];
            s1 += sacc[j][2] + sacc[j][3];
        }
        s0 += __shfl_xor_sync(0xffffffffu, s0, 1);
        s0 += __shfl_xor_sync(0xffffffffu, s0, 2);
        s1 += __shfl_xor_sync(0xffffffffu, s1, 1);
        s1 += __shfl_xor_sync(0xffffffffu, s1, 2);
        l0 = l0 * c0 + s0;
        l1 = l1 * c1 + s1;
#pragma unroll
        for (int j = 0; j < 8; ++j) {
            oacc[j][0] *= c0; oacc[j][1] *= c0;
            oacc[j][2] *= c1; oacc[j][3] *= c1;
        }

        // P (fp16) to warp-private rows of Ps
#pragma unroll
        for (int j = 0; j < 8; ++j) {
            int cb = j * 8 + 2 * tg;
            *(uint32_t*)(Ps + (wm + g) * 72 + cb) = pack2(sacc[j][0], sacc[j][1]);
            *(uint32_t*)(Ps + (wm + g + 8) * 72 + cb) = pack2(sacc[j][2], sacc[j][3]);
        }
        __syncwarp();

        // O += P V
#pragma unroll
        for (int ks = 0; ks < 4; ++ks) {
            uint32_t a0 = LDH32(Ps, (wm + g) * 72 + ks * 16 + 2 * tg);
            uint32_t a1 = LDH32(Ps, (wm + g + 8) * 72 + ks * 16 + 2 * tg);
            uint32_t a2 = LDH32(Ps, (wm + g) * 72 + ks * 16 + 2 * tg + 8);
            uint32_t a3 = LDH32(Ps, (wm + g + 8) * 72 + ks * 16 + 2 * tg + 8);
#pragma unroll
            for (int j = 0; j < 8; ++j) {
                uint32_t b0 = LDH32(Vt, (j * 8 + g) * 72 + ks * 16 + 2 * tg);
                uint32_t b1 = LDH32(Vt, (j * 8 + g) * 72 + ks * 16 + 2 * tg + 8);
                mma_f16(oacc[j], a0, a1, a2, a3, b0, b1);
            }
        }
    }

    // normalize + store fp16
    float inv0 = 1.0f / l0, inv1 = 1.0f / l1;
#pragma unroll
    for (int j = 0; j < 8; ++j) {
        int cb = j * 8 + 2 * tg;
        *(uint32_t*)(obp + (wm + g) * DIM + cb) =
            pack2(oacc[j][0] * inv0, oacc[j][1] * inv0);
        *(uint32_t*)(obp + (wm + g + 8) * DIM + cb) =
            pack2(oacc[j][2] * inv1, oacc[j][3] * inv1);
    }
}

// local: 2048 blocks = b(2) | w(3) | h(4) | qt(2)
__global__ __launch_bounds__(256, 2) void local_attn_kernel() {
    int bx = blockIdx.x;
    int qt = bx & 3;
    int h = (bx >> 2) & 15;
    int w = (bx >> 6) & 7;
    int b = bx >> 9;
    const float* base = g_xpos + (b * SEQ + w * WINS) * DIM + h * HDIM;
    const float* qb = base + (qt * 128) * DIM;
    __half* ob = g_local + (b * SEQ + w * WINS + qt * 128) * DIM + h * HDIM;
    flash_mma(qb, base, ob, 8);
}

// global: 2048 blocks = b(2) | h(4) | qt(5)
__global__ __launch_bounds__(256, 2) void global_attn_kernel() {
    int bx = blockIdx.x;
    int qt = bx & 31;
    int h = (bx >> 5) & 15;
    int b = bx >> 9;
    const float* qb = g_xpos + (b * SEQ + qt * 128) * DIM + h * HDIM;
    const float* kb = g_gt + (b * NGT) * DIM + h * HDIM;
    __half* ob = g_glob + (b * SEQ + qt * 128) * DIM + h * HDIM;
    flash_mma(qb, kb, ob, 2);
}

// ============== pipelined fp16 mma GEMM, 128x128 tile, KT=32 halves ==============
// smem per stage (halves): A[128][40] + B[128][40] = 10240 halves = 20 KB.
#define STG_H 10240
#define GP_SMEM (2 * STG_H * 2)

template <int MODE>
__device__ __forceinline__ void gp_load(__half* sm, int s, int m0, int n0, int k0,
                                        const __half* Bsrc, int tid) {
    __half* A = sm + s * STG_H;
    __half* B = A + 5120;
    constexpr int KTOT = (MODE == 0) ? 4096 : (MODE == 1) ? 2048 : 1024;
#pragma unroll
    for (int t = 0; t < 2; ++t) {
        int id = tid + t * 256;          // 0..511
        int r = id >> 2, q = id & 3;     // row, 16B segment (8 halves)
        int kk = k0 + q * 8;
        const __half* src;
        if (MODE == 0) {
            src = g_convA + (m0 + r) * 4096 + kk;
        } else if (MODE == 1) {
            src = (kk < 1024) ? g_local + (m0 + r) * 1024 + kk
                              : g_glob + (m0 + r) * 1024 + (kk - 1024);
        } else {
            src = g_mixed + (m0 + r) * 1024 + kk;
        }
        cp_async16(smem_u32(A + r * 40 + q * 8), src);
    }
#pragma unroll
    for (int t = 0; t < 2; ++t) {
        int id = tid + t * 256;
        int r = id >> 2, q = id & 3;
        cp_async16(smem_u32(B + r * 40 + q * 8), Bsrc + (n0 + r) * KTOT + k0 + q * 8);
    }
    cp_commit();
}

template <int MODE>
__global__ __launch_bounds__(256) void gemm_pipe(const float* __restrict__ bias,
                                                 float* __restrict__ Cext) {
    constexpr int NIT = (MODE == 0) ? 16 : (MODE == 1) ? 64 : 32;
    extern __shared__ __half smh[];
    const int tid = threadIdx.x;
    const int warp = tid >> 5, lane = tid & 31;
    const int g = lane >> 2, tg = lane & 3;
    const int wm = (warp >> 1) * 32, wn = (warp & 1) * 64;
    const int m0 = blockIdx.y * 128, n0 = blockIdx.x * 128;
    const int kbase = (MODE == 0) ? blockIdx.z * 512 : 0;
    const __half* Bsrc = (MODE == 0) ? g_cwT : (MODE == 1) ? g_gwT : g_owT;

    float acc[2][8][4];
#pragma unroll
    for (int mt = 0; mt < 2; ++mt)
#pragma unroll
        for (int j = 0; j < 8; ++j)
#pragma unroll
            for (int q = 0; q < 4; ++q) acc[mt][j][q] = 0.f;

    gp_load<MODE>(smh, 0, m0, n0, kbase, Bsrc, tid);

    for (int i = 0; i < NIT; ++i) {
        if (i + 1 < NIT) {
            gp_load<MODE>(smh, (i + 1) & 1, m0, n0, kbase + (i + 1) * 32, Bsrc, tid);
            asm volatile("cp.async.wait_group 1;" ::: "memory");
        } else {
            asm volatile("cp.async.wait_group 0;" ::: "memory");
        }
        __syncthreads();

        const __half* As = smh + (i & 1) * STG_H;
        const __half* Bs = As + 5120;
#pragma unroll
        for (int ks = 0; ks < 2; ++ks) {
            uint32_t bf[8][2];
#pragma unroll
            for (int j = 0; j < 8; ++j) {
                int n = wn + j * 8 + g;
                bf[j][0] = LDH32(Bs, n * 40 + ks * 16 + 2 * tg);
                bf[j][1] = LDH32(Bs, n * 40 + ks * 16 + 2 * tg + 8);
            }
#pragma unroll
            for (int mt = 0; mt < 2; ++mt) {
                int r0 = wm + mt * 16 + g;
                uint32_t a0 = LDH32(As, r0 * 40 + ks * 16 + 2 * tg);
                uint32_t a1 = LDH32(As, (r0 + 8) * 40 + ks * 16 + 2 * tg);
                uint32_t a2 = LDH32(As, r0 * 40 + ks * 16 + 2 * tg + 8);
                uint32_t a3 = LDH32(As, (r0 + 8) * 40 + ks * 16 + 2 * tg + 8);
#pragma unroll
                for (int j = 0; j < 8; ++j)
                    mma_f16(acc[mt][j], a0, a1, a2, a3, bf[j][0], bf[j][1]);
            }
        }
        __syncthreads();
    }

    // ---- epilogue ----
#pragma unroll
    for (int mt = 0; mt < 2; ++mt) {
#pragma unroll
        for (int j = 0; j < 8; ++j) {
            int col = n0 + wn + j * 8 + 2 * tg;
            int ra = m0 + wm + mt * 16 + g;
            int rb = ra + 8;
            if (MODE == 0) {
                atomicAdd(&g_comp[ra * 1024 + col], acc[mt][j][0]);
                atomicAdd(&g_comp[ra * 1024 + col + 1], acc[mt][j][1]);
                atomicAdd(&g_comp[rb * 1024 + col], acc[mt][j][2]);
                atomicAdd(&g_comp[rb * 1024 + col + 1], acc[mt][j][3]);
                continue;
            }
            float2 bz = *(const float2*)&bias[col];
            float z0x = acc[mt][j][0] + bz.x, z0y = acc[mt][j][1] + bz.y;
            float z1x = acc[mt][j][2] + bz.x, z1y = acc[mt][j][3] + bz.y;
            if (MODE == 1) {
                int ia = ra * 1024 + col, ib = rb * 1024 + col;
                float2 la = __half22float2(*(const __half2*)(g_local + ia));
                float2 lb = __half22float2(*(const __half2*)(g_local + ib));
                float2 ga = __half22float2(*(const __half2*)(g_glob + ia));
                float2 gb = __half22float2(*(const __half2*)(g_glob + ib));
                float s0x = 1.0f / (1.0f + fexp(-z0x));
                float s0y = 1.0f / (1.0f + fexp(-z0y));
                float s1x = 1.0f / (1.0f + fexp(-z1x));
                float s1y = 1.0f / (1.0f + fexp(-z1y));
                *(uint32_t*)(g_mixed + ia) =
                    pack2(s0x * la.x + (1.f - s0x) * ga.x,
                          s0y * la.y + (1.f - s0y) * ga.y);
                *(uint32_t*)(g_mixed + ib) =
                    pack2(s1x * lb.x + (1.f - s1x) * gb.x,
                          s1y * lb.y + (1.f - s1y) * gb.y);
            } else {
                *(float2*)&Cext[ra * 1024 + col] = make_float2(z0x, z0y);
                *(float2*)&Cext[rb * 1024 + col] = make_float2(z1x, z1y);
            }
        }
    }
}

// ---------------- launch ----------------
extern "C" void kernel_launch(void* const* d_in, const int* in_sizes, int n_in,
                              void* d_out, int out_size) {
    const float* x = (const float*)d_in[0];
    const float* pe = (const float*)d_in[1];
    const float* gm = (const float*)d_in[2];
    const float* cw = (const float*)d_in[3];
    const float* cb = (const float*)d_in[4];
    const float* gw = (const float*)d_in[5];
    const float* gb = (const float*)d_in[6];
    const float* ow = (const float*)d_in[7];
    const float* ob = (const float*)d_in[8];
    float* out = (float*)d_out;

    cudaFuncSetAttribute((const void*)local_attn_kernel,
                         cudaFuncAttributeMaxDynamicSharedMemorySize, 36864);
    cudaFuncSetAttribute((const void*)global_attn_kernel,
                         cudaFuncAttributeMaxDynamicSharedMemorySize, 36864);
    cudaFuncSetAttribute((const void*)gemm_pipe<0>,
                         cudaFuncAttributeMaxDynamicSharedMemorySize, GP_SMEM);
    cudaFuncSetAttribute((const void*)gemm_pipe<1>,
                         cudaFuncAttributeMaxDynamicSharedMemorySize, GP_SMEM);
    cudaFuncSetAttribute((const void*)gemm_pipe<2>,
                         cudaFuncAttributeMaxDynamicSharedMemorySize, GP_SMEM);

    add_pos_kernel<<<16384, 256>>>(x, pe);
    {
        __half* gwT; __half* owT;
        cudaGetSymbolAddress((void**)&gwT, g_gwT);
        cudaGetSymbolAddress((void**)&owT, g_owT);
        transpose_kernel<<<dim3(32, 64), 256>>>(gw, gwT, 2048, 1024);
        transpose_kernel<<<dim3(32, 32), 256>>>(ow, owT, 1024, 1024);
    }
    im2col_kernel<<<1024, 256>>>();
    cw_rearrange_kernel<<<4096, 256>>>(cw);
    zero_comp_kernel<<<256, 256>>>();
    gemm_pipe<0><<<dim3(8, 2, 8), 256, GP_SMEM>>>(nullptr, nullptr);  // conv split-K
    conv_scatter_kernel<<<256, 256>>>(cb);
    gt_fill_kernel<<<256, 256>>>(gm);
    local_attn_kernel<<<2048, 256, 36864>>>();
    global_attn_kernel<<<2048, 256, 36864>>>();
    gemm_pipe<1><<<dim3(8, 128), 256, GP_SMEM>>>(gb, nullptr);  // gate + mix
    gemm_pipe<2><<<dim3(8, 128), 256, GP_SMEM>>>(ob, out);      // output projection
}

// round 8
// speedup vs baseline: 5.8949x; 1.0401x over previous
#include <cuda_runtime.h>
#include <cuda_fp16.h>
#include <cstdint>

#define NB 4
#define SEQ 4096
#define DIM 1024
#define NH 16
#define HDIM 64
#define WINS 512
#define NWIN 8
#define NGT 128

// ---------------- scratch (static device globals; no allocation) ----------------
__device__ __half g_xph[NB * SEQ * DIM];     // x + pos_emb (fp16)
__device__ __half g_local[NB * SEQ * DIM];   // local attention out
__device__ __half g_glob[NB * SEQ * DIM];    // global attention out
__device__ __half g_mixed[NB * SEQ * DIM];   // gated mix
__device__ __half g_gth[NB * NGT * DIM];     // [comp ; global_memory] per batch (fp16)
__device__ __half g_gwT[DIM * 2 * DIM];      // gate_w transposed [1024][2048]
__device__ __half g_owT[DIM * DIM];          // out_w transposed  [1024][1024]
__device__ __half g_convA[256 * 4096];       // im2col A
__device__ __half g_cwT[DIM * 4096];         // conv_w rearranged [dout][ktap*1024+din]
__device__ float g_comp[256 * DIM];          // conv split-K accumulator (fp32)

// ---------------- helpers ----------------
__device__ __forceinline__ uint32_t pack2(float a, float b) {
    __half2 h = __floats2half2_rn(a, b);
    return *(uint32_t*)&h;
}
__device__ __forceinline__ uint32_t smem_u32(const void* p) {
    uint32_t a;
    asm("{ .reg .u64 t; cvta.to.shared.u64 t, %1; cvt.u32.u64 %0, t; }"
        : "=r"(a) : "l"(p));
    return a;
}
__device__ __forceinline__ void cp_async16(uint32_t dst, const void* src) {
    asm volatile("cp.async.cg.shared.global [%0], [%1], 16;"
                 :: "r"(dst), "l"(__cvta_generic_to_global(src)) : "memory");
}
__device__ __forceinline__ void cp_commit() {
    asm volatile("cp.async.commit_group;" ::: "memory");
}

// fast exp on fma/alu pipes (no MUFU). |rel err| ~2e-6 for x <= 0.
__device__ __forceinline__ float fexp(float x) {
    float z = fmaxf(x, -87.3365f) * 1.4426950408889634f;
    float s = z + 12582912.0f;
    int n = __float_as_int(s) - 0x4b400000;
    float f = z - (s - 12582912.0f);
    float p = 1.3371542e-3f;
    p = fmaf(p, f, 9.6181291e-3f);
    p = fmaf(p, f, 5.5504109e-2f);
    p = fmaf(p, f, 2.4022651e-1f);
    p = fmaf(p, f, 6.9314718e-1f);
    p = fmaf(p, f, 1.0f);
    return __int_as_float(__float_as_int(p) + (n << 23));
}

// fp16 mma with fp32 accum: D = A(16x16) B(16x8) + D
__device__ __forceinline__ void mma_f16(float* c, uint32_t a0, uint32_t a1,
                                        uint32_t a2, uint32_t a3,
                                        uint32_t b0, uint32_t b1) {
    asm volatile(
        "mma.sync.aligned.m16n8k16.row.col.f32.f16.f16.f32 "
        "{%0,%1,%2,%3}, {%4,%5,%6,%7}, {%8,%9}, {%0,%1,%2,%3};"
        : "+f"(c[0]), "+f"(c[1]), "+f"(c[2]), "+f"(c[3])
        : "r"(a0), "r"(a1), "r"(a2), "r"(a3), "r"(b0), "r"(b1));
}

#define LDH32(arr, idx) (*(const uint32_t*)((arr) + (idx)))

// ---------------- kernel: x + pos_emb -> fp16 ----------------
__global__ __launch_bounds__(256) void add_pos_kernel(const float* __restrict__ x,
                                                      const float* __restrict__ pe) {
    int i = blockIdx.x * 256 + threadIdx.x;  // 4,194,304 groups of 4 floats
    float4 a = ((const float4*)x)[i];
    float4 p = ((const float4*)pe)[i & 1048575];
    ((uint2*)g_xph)[i] = make_uint2(pack2(a.x + p.x, a.y + p.y),
                                    pack2(a.z + p.z, a.w + p.w));
}

// ---------------- fill global_memory half of gt (fp16) ----------------
__global__ __launch_bounds__(256) void gt_fill_kernel(const float* __restrict__ gm) {
    int i = blockIdx.x * 256 + threadIdx.x;  // 65536 groups of 4
    float4 v = ((const float4*)gm)[i & 16383];
    *(uint2*)(g_gth + (i >> 14) * 131072 + 65536 + (i & 16383) * 4) =
        make_uint2(pack2(v.x, v.y), pack2(v.z, v.w));
}

// ---------------- transpose + fp16: in[K][N] -> out[N][K] ----------------
__global__ __launch_bounds__(256) void transpose_kernel(const float* __restrict__ in,
                                                        __half* __restrict__ out,
                                                        int K, int N) {
    __shared__ float t[32][33];
    int bx = blockIdx.x * 32;
    int by = blockIdx.y * 32;
    int x = threadIdx.x & 31, y = threadIdx.x >> 5;
#pragma unroll
    for (int i = 0; i < 32; i += 8) t[y + i][x] = in[(by + y + i) * N + bx + x];
    __syncthreads();
#pragma unroll
    for (int i = 0; i < 32; i += 8)
        out[(bx + y + i) * K + by + x] = __float2half_rn(t[x][y + i]);
}

// ---------------- conv pre-transforms ----------------
// im2col from fp16 xph: A[(b*64+g)][ktap*1024+din] = xph[b][4g+ktap][din]
__global__ __launch_bounds__(256) void im2col_kernel() {
    int i = blockIdx.x * 256 + threadIdx.x;  // 131072 groups of 8 halves
    int r = i >> 9, c8 = (i & 511) << 3;
    int ktap = c8 >> 10, din = c8 & 1023;
    int b = r >> 6, g = r & 63;
    uint4 v = *(const uint4*)(g_xph + ((b << 12) + (g << 2) + ktap) * DIM + din);
    *(uint4*)(g_convA + r * 4096 + c8) = v;
}

__global__ __launch_bounds__(256) void cw_rearrange_kernel(const float* __restrict__ cw) {
    int i = blockIdx.x * 256 + threadIdx.x;  // 1048576 groups of 4
    int dout = i >> 10, q = i & 1023;
    int c4 = q << 2;
    int ktap = c4 >> 10, din = c4 & 1023;
    const float* base = cw + dout * 4096 + din * 4 + ktap;
    *(uint2*)(g_cwT + dout * 4096 + c4) =
        make_uint2(pack2(base[0], base[4]), pack2(base[8], base[12]));
}

__global__ __launch_bounds__(256) void zero_comp_kernel() {
    int i = blockIdx.x * 256 + threadIdx.x;
    ((float4*)g_comp)[i] = make_float4(0.f, 0.f, 0.f, 0.f);
}

// comp + bias -> gth rows (b*128 + g), fp16
__global__ __launch_bounds__(256) void conv_scatter_kernel(const float* __restrict__ cb) {
    int i = blockIdx.x * 256 + threadIdx.x;  // 65536 groups of 4
    int r = i >> 8, c4 = (i & 255) << 2;
    float4 v = *(const float4*)(g_comp + r * 1024 + c4);
    float4 b = *(const float4*)(cb + c4);
    int outr = ((r >> 6) << 7) | (r & 63);
    *(uint2*)(g_gth + outr * 1024 + c4) =
        make_uint2(pack2(v.x + b.x, v.y + b.y), pack2(v.z + b.z, v.w + b.w));
}

// ============= fp16 tensor-core flash attention (128 q-rows, 8 warps) =============
// smem (halves): Ks[64][72], Vt[64][72] ([d][key]), Ps[128][72]. 36864 bytes.
__device__ __forceinline__ void flash_mma(const __half* __restrict__ qb,
                                          const __half* __restrict__ kb,
                                          __half* __restrict__ obp, int nkt) {
    extern __shared__ __half smh[];
    __half* Ks = smh;            // 4608 halves
    __half* Vt = smh + 4608;     // 4608 halves
    __half* Ps = smh + 9216;     // 9216 halves
    const int tid = threadIdx.x;
    const int warp = tid >> 5, lane = tid & 31;
    const int g = lane >> 2, tg = lane & 3;
    const int wm = warp * 16;

    // stage Q (scaled by 1/8, exact in fp16) into Ps
    const __half2 sc2 = __float2half2_rn(0.125f);
#pragma unroll
    for (int it = 0; it < 4; ++it) {
        int f = tid + it * 256;            // 1024 slots: 128 rows x 8 (8 halves each)
        int row = f >> 3, c8 = (f & 7) << 3;
        uint4 v = *(const uint4*)(qb + row * DIM + c8);
        __half2* hv = (__half2*)&v;
#pragma unroll
        for (int j = 0; j < 4; ++j) hv[j] = __hmul2(hv[j], sc2);
        *(uint4*)(Ps + row * 72 + c8) = v;
    }
    __syncthreads();

    // Q fragments (register-resident), 4 k-steps of 16
    uint32_t qf[4][4];
#pragma unroll
    for (int ks = 0; ks < 4; ++ks) {
        qf[ks][0] = LDH32(Ps, (wm + g) * 72 + ks * 16 + 2 * tg);
        qf[ks][1] = LDH32(Ps, (wm + g + 8) * 72 + ks * 16 + 2 * tg);
        qf[ks][2] = LDH32(Ps, (wm + g) * 72 + ks * 16 + 2 * tg + 8);
        qf[ks][3] = LDH32(Ps, (wm + g + 8) * 72 + ks * 16 + 2 * tg + 8);
    }

    float m0 = -1e30f, m1 = -1e30f, l0 = 0.f, l1 = 0.f;
    float oacc[8][4];
#pragma unroll
    for (int j = 0; j < 8; ++j)
#pragma unroll
        for (int q = 0; q < 4; ++q) oacc[j][q] = 0.f;

    for (int kt = 0; kt < nkt; ++kt) {
        __syncthreads();
        // K(=V) tile: row-major Ks + transposed Vt (straight fp16 copies)
#pragma unroll
        for (int it = 0; it < 2; ++it) {
            int f = tid + it * 256;        // 512 slots: 64 rows x 8
            int row = f >> 3, c8 = (f & 7) << 3;
            uint4 v = *(const uint4*)(kb + (kt * 64 + row) * DIM + c8);
            *(uint4*)(Ks + row * 72 + c8) = v;
            const __half* hv = (const __half*)&v;
#pragma unroll
            for (int j = 0; j < 8; ++j) Vt[(c8 + j) * 72 + row] = hv[j];
        }
        __syncthreads();

        // S = Q K^T
        float sacc[8][4];
#pragma unroll
        for (int j = 0; j < 8; ++j)
#pragma unroll
            for (int q = 0; q < 4; ++q) sacc[j][q] = 0.f;
#pragma unroll
        for (int ks = 0; ks < 4; ++ks) {
#pragma unroll
            for (int j = 0; j < 8; ++j) {
                uint32_t b0 = LDH32(Ks, (j * 8 + g) * 72 + ks * 16 + 2 * tg);
                uint32_t b1 = LDH32(Ks, (j * 8 + g) * 72 + ks * 16 + 2 * tg + 8);
                mma_f16(sacc[j], qf[ks][0], qf[ks][1], qf[ks][2], qf[ks][3], b0, b1);
            }
        }

        // online softmax (quad-local reductions)
        float mx0 = -1e30f, mx1 = -1e30f;
#pragma unroll
        for (int j = 0; j < 8; ++j) {
            mx0 = fmaxf(mx0, fmaxf(sacc[j][0], sacc[j][1]));
            mx1 = fmaxf(mx1, fmaxf(sacc[j][2], sacc[j][3]));
        }
        mx0 = fmaxf(mx0, __shfl_xor_sync(0xffffffffu, mx0, 1));
        mx0 = fmaxf(mx0, __shfl_xor_sync(0xffffffffu, mx0, 2));
        mx1 = fmaxf(mx1, __shfl_xor_sync(0xffffffffu, mx1, 1));
        mx1 = fmaxf(mx1, __shfl_xor_sync(0xffffffffu, mx1, 2));
        float mn0 = fmaxf(m0, mx0), mn1 = fmaxf(m1, mx1);
        float c0 = fexp(m0 - mn0), c1 = fexp(m1 - mn1);
        m0 = mn0; m1 = mn1;
        float s0 = 0.f, s1 = 0.f;
#pragma unroll
        for (int j = 0; j < 8; ++j) {
            sacc[j][0] = fexp(sacc[j][0] - mn0);
            sacc[j][1] = fexp(sacc[j][1] - mn0);
            sacc[j][2] = fexp(sacc[j][2] - mn1);
            sacc[j][3] = fexp(sacc[j][3] - mn1);
            s0 += sacc[j][0] + sacc[j][1];
            s1 += sacc[j][2] + sacc[j][3];
        }
        s0 += __shfl_xor_sync(0xffffffffu, s0, 1);
        s0 += __shfl_xor_sync(0xffffffffu, s0, 2);
        s1 += __shfl_xor_sync(0xffffffffu, s1, 1);
        s1 += __shfl_xor_sync(0xffffffffu, s1, 2);
        l0 = l0 * c0 + s0;
        l1 = l1 * c1 + s1;
#pragma unroll
        for (int j = 0; j < 8; ++j) {
            oacc[j][0] *= c0; oacc[j][1] *= c0;
            oacc[j][2] *= c1; oacc[j][3] *= c1;
        }

        // P (fp16) to warp-private rows of Ps
#pragma unroll
        for (int j = 0; j < 8; ++j) {
            int cb = j * 8 + 2 * tg;
            *(uint32_t*)(Ps + (wm + g) * 72 + cb) = pack2(sacc[j][0], sacc[j][1]);
            *(uint32_t*)(Ps + (wm + g + 8) * 72 + cb) = pack2(sacc[j][2], sacc[j][3]);
        }
        __syncwarp();

        // O += P V
#pragma unroll
        for (int ks = 0; ks < 4; ++ks) {
            uint32_t a0 = LDH32(Ps, (wm + g) * 72 + ks * 16 + 2 * tg);
            uint32_t a1 = LDH32(Ps, (wm + g + 8) * 72 + ks * 16 + 2 * tg);
            uint32_t a2 = LDH32(Ps, (wm + g) * 72 + ks * 16 + 2 * tg + 8);
            uint32_t a3 = LDH32(Ps, (wm + g + 8) * 72 + ks * 16 + 2 * tg + 8);
#pragma unroll
            for (int j = 0; j < 8; ++j) {
                uint32_t b0 = LDH32(Vt, (j * 8 + g) * 72 + ks * 16 + 2 * tg);
                uint32_t b1 = LDH32(Vt, (j * 8 + g) * 72 + ks * 16 + 2 * tg + 8);
                mma_f16(oacc[j], a0, a1, a2, a3, b0, b1);
            }
        }
    }

    // normalize + store fp16
    float inv0 = 1.0f / l0, inv1 = 1.0f / l1;
#pragma unroll
    for (int j = 0; j < 8; ++j) {
        int cb = j * 8 + 2 * tg;
        *(uint32_t*)(obp + (wm + g) * DIM + cb) =
            pack2(oacc[j][0] * inv0, oacc[j][1] * inv0);
        *(uint32_t*)(obp + (wm + g + 8) * DIM + cb) =
            pack2(oacc[j][2] * inv1, oacc[j][3] * inv1);
    }
}

// merged attention: blocks [0,2048) local, [2048,4096) global
__global__ __launch_bounds__(256, 2) void attn_kernel() {
    int bx = blockIdx.x;
    if (bx < 2048) {
        int qt = bx & 3;
        int h = (bx >> 2) & 15;
        int w = (bx >> 6) & 7;
        int b = bx >> 9;
        const __half* base = g_xph + (b * SEQ + w * WINS) * DIM + h * HDIM;
        const __half* qb = base + (qt * 128) * DIM;
        __half* ob = g_local + (b * SEQ + w * WINS + qt * 128) * DIM + h * HDIM;
        flash_mma(qb, base, ob, 8);
    } else {
        bx -= 2048;
        int qt = bx & 31;
        int h = (bx >> 5) & 15;
        int b = bx >> 9;
        const __half* qb = g_xph + (b * SEQ + qt * 128) * DIM + h * HDIM;
        const __half* kb = g_gth + b * NGT * DIM + h * HDIM;
        __half* ob = g_glob + (b * SEQ + qt * 128) * DIM + h * HDIM;
        flash_mma(qb, kb, ob, 2);
    }
}

// ============== pipelined fp16 mma GEMM, 128x128 tile, KT=32 halves ==============
#define STG_H 10240
#define GP_SMEM (2 * STG_H * 2)

template <int MODE>
__device__ __forceinline__ void gp_load(__half* sm, int s, int m0, int n0, int k0,
                                        const __half* Bsrc, int tid) {
    __half* A = sm + s * STG_H;
    __half* B = A + 5120;
    constexpr int KTOT = (MODE == 0) ? 4096 : (MODE == 1) ? 2048 : 1024;
#pragma unroll
    for (int t = 0; t < 2; ++t) {
        int id = tid + t * 256;
        int r = id >> 2, q = id & 3;
        int kk = k0 + q * 8;
        const __half* src;
        if (MODE == 0) {
            src = g_convA + (m0 + r) * 4096 + kk;
        } else if (MODE == 1) {
            src = (kk < 1024) ? g_local + (m0 + r) * 1024 + kk
                              : g_glob + (m0 + r) * 1024 + (kk - 1024);
        } else {
            src = g_mixed + (m0 + r) * 1024 + kk;
        }
        cp_async16(smem_u32(A + r * 40 + q * 8), src);
    }
#pragma unroll
    for (int t = 0; t < 2; ++t) {
        int id = tid + t * 256;
        int r = id >> 2, q = id & 3;
        cp_async16(smem_u32(B + r * 40 + q * 8), Bsrc + (n0 + r) * KTOT + k0 + q * 8);
    }
    cp_commit();
}

template <int MODE>
__global__ __launch_bounds__(256) void gemm_pipe(const float* __restrict__ bias,
                                                 float* __restrict__ Cext) {
    constexpr int NIT = (MODE == 0) ? 16 : (MODE == 1) ? 64 : 32;
    extern __shared__ __half smh[];
    const int tid = threadIdx.x;
    const int warp = tid >> 5, lane = tid & 31;
    const int g = lane >> 2, tg = lane & 3;
    const int wm = (warp >> 1) * 32, wn = (warp & 1) * 64;
    const int m0 = blockIdx.y * 128, n0 = blockIdx.x * 128;
    const int kbase = (MODE == 0) ? blockIdx.z * 512 : 0;
    const __half* Bsrc = (MODE == 0) ? g_cwT : (MODE == 1) ? g_gwT : g_owT;

    float acc[2][8][4];
#pragma unroll
    for (int mt = 0; mt < 2; ++mt)
#pragma unroll
        for (int j = 0; j < 8; ++j)
#pragma unroll
            for (int q = 0; q < 4; ++q) acc[mt][j][q] = 0.f;

    gp_load<MODE>(smh, 0, m0, n0, kbase, Bsrc, tid);

    for (int i = 0; i < NIT; ++i) {
        if (i + 1 < NIT) {
            gp_load<MODE>(smh, (i + 1) & 1, m0, n0, kbase + (i + 1) * 32, Bsrc, tid);
            asm volatile("cp.async.wait_group 1;" ::: "memory");
        } else {
            asm volatile("cp.async.wait_group 0;" ::: "memory");
        }
        __syncthreads();

        const __half* As = smh + (i & 1) * STG_H;
        const __half* Bs = As + 5120;
#pragma unroll
        for (int ks = 0; ks < 2; ++ks) {
            uint32_t bf[8][2];
#pragma unroll
            for (int j = 0; j < 8; ++j) {
                int n = wn + j * 8 + g;
                bf[j][0] = LDH32(Bs, n * 40 + ks * 16 + 2 * tg);
                bf[j][1] = LDH32(Bs, n * 40 + ks * 16 + 2 * tg + 8);
            }
#pragma unroll
            for (int mt = 0; mt < 2; ++mt) {
                int r0 = wm + mt * 16 + g;
                uint32_t a0 = LDH32(As, r0 * 40 + ks * 16 + 2 * tg);
                uint32_t a1 = LDH32(As, (r0 + 8) * 40 + ks * 16 + 2 * tg);
                uint32_t a2 = LDH32(As, r0 * 40 + ks * 16 + 2 * tg + 8);
                uint32_t a3 = LDH32(As, (r0 + 8) * 40 + ks * 16 + 2 * tg + 8);
#pragma unroll
                for (int j = 0; j < 8; ++j)
                    mma_f16(acc[mt][j], a0, a1, a2, a3, bf[j][0], bf[j][1]);
            }
        }
        __syncthreads();
    }

    // ---- epilogue ----
#pragma unroll
    for (int mt = 0; mt < 2; ++mt) {
#pragma unroll
        for (int j = 0; j < 8; ++j) {
            int col = n0 + wn + j * 8 + 2 * tg;
            int ra = m0 + wm + mt * 16 + g;
            int rb = ra + 8;
            if (MODE == 0) {
                atomicAdd(&g_comp[ra * 1024 + col], acc[mt][j][0]);
                atomicAdd(&g_comp[ra * 1024 + col + 1], acc[mt][j][1]);
                atomicAdd(&g_comp[rb * 1024 + col], acc[mt][j][2]);
                atomicAdd(&g_comp[rb * 1024 + col + 1], acc[mt][j][3]);
                continue;
            }
            float2 bz = *(const float2*)&bias[col];
            float z0x = acc[mt][j][0] + bz.x, z0y = acc[mt][j][1] + bz.y;
            float z1x = acc[mt][j][2] + bz.x, z1y = acc[mt][j][3] + bz.y;
            if (MODE == 1) {
                int ia = ra * 1024 + col, ib = rb * 1024 + col;
                float2 la = __half22float2(*(const __half2*)(g_local + ia));
                float2 lb = __half22float2(*(const __half2*)(g_local + ib));
                float2 ga = __half22float2(*(const __half2*)(g_glob + ia));
                float2 gb = __half22float2(*(const __half2*)(g_glob + ib));
                float s0x = 1.0f / (1.0f + fexp(-z0x));
                float s0y = 1.0f / (1.0f + fexp(-z0y));
                float s1x = 1.0f / (1.0f + fexp(-z1x));
                float s1y = 1.0f / (1.0f + fexp(-z1y));
                *(uint32_t*)(g_mixed + ia) =
                    pack2(s0x * la.x + (1.f - s0x) * ga.x,
                          s0y * la.y + (1.f - s0y) * ga.y);
                *(uint32_t*)(g_mixed + ib) =
                    pack2(s1x * lb.x + (1.f - s1x) * gb.x,
                          s1y * lb.y + (1.f - s1y) * gb.y);
            } else {
                *(float2*)&Cext[ra * 1024 + col] = make_float2(z0x, z0y);
                *(float2*)&Cext[rb * 1024 + col] = make_float2(z1x, z1y);
            }
        }
    }
}

// ---------------- launch ----------------
extern "C" void kernel_launch(void* const* d_in, const int* in_sizes, int n_in,
                              void* d_out, int out_size) {
    const float* x = (const float*)d_in[0];
    const float* pe = (const float*)d_in[1];
    const float* gm = (const float*)d_in[2];
    const float* cw = (const float*)d_in[3];
    const float* cb = (const float*)d_in[4];
    const float* gw = (const float*)d_in[5];
    const float* gb = (const float*)d_in[6];
    const float* ow = (const float*)d_in[7];
    const float* ob = (const float*)d_in[8];
    float* out = (float*)d_out;

    cudaFuncSetAttribute((const void*)attn_kernel,
                         cudaFuncAttributeMaxDynamicSharedMemorySize, 36864);
    cudaFuncSetAttribute((const void*)gemm_pipe<0>,
                         cudaFuncAttributeMaxDynamicSharedMemorySize, GP_SMEM);
    cudaFuncSetAttribute((const void*)gemm_pipe<1>,
                         cudaFuncAttributeMaxDynamicSharedMemorySize, GP_SMEM);
    cudaFuncSetAttribute((const void*)gemm_pipe<2>,
                         cudaFuncAttributeMaxDynamicSharedMemorySize, GP_SMEM);

    add_pos_kernel<<<16384, 256>>>(x, pe);
    {
        __half* gwT; __half* owT;
        cudaGetSymbolAddress((void**)&gwT, g_gwT);
        cudaGetSymbolAddress((void**)&owT, g_owT);
        transpose_kernel<<<dim3(32, 64), 256>>>(gw, gwT, 2048, 1024);
        transpose_kernel<<<dim3(32, 32), 256>>>(ow, owT, 1024, 1024);
    }
    im2col_kernel<<<512, 256>>>();
    cw_rearrange_kernel<<<4096, 256>>>(cw);
    zero_comp_kernel<<<256, 256>>>();
    gemm_pipe<0><<<dim3(8, 2, 8), 256, GP_SMEM>>>(nullptr, nullptr);  // conv split-K
    conv_scatter_kernel<<<256, 256>>>(cb);
    gt_fill_kernel<<<256, 256>>>(gm);
    attn_kernel<<<4096, 256, 36864>>>();
    gemm_pipe<1><<<dim3(8, 128), 256, GP_SMEM>>>(gb, nullptr);  // gate + mix
    gemm_pipe<2><<<dim3(8, 128), 256, GP_SMEM>>>(ob, out);      // output projection
}

// round 9
// speedup vs baseline: 6.7492x; 1.1449x over previous
#include <cuda_runtime.h>
#include <cuda_fp16.h>
#include <cstdint>

#define NB 4
#define SEQ 4096
#define DIM 1024
#define NH 16
#define HDIM 64
#define WINS 512
#define NWIN 8
#define NGT 128

// ---------------- scratch (static device globals; no allocation) ----------------
__device__ __half g_xph[NB * SEQ * DIM];     // x + pos_emb (fp16)
__device__ __half g_local[NB * SEQ * DIM];   // local attention out
__device__ __half g_glob[NB * SEQ * DIM];    // global attention out
__device__ __half g_mixed[NB * SEQ * DIM];   // gated mix
__device__ __half g_gth[NB * NGT * DIM];     // [comp ; global_memory] per batch (fp16)
__device__ __half g_gwT[DIM * 2 * DIM];      // gate_w transposed [1024][2048]
__device__ __half g_owT[DIM * DIM];          // out_w transposed  [1024][1024]
__device__ __half g_cwT[DIM * 4096];         // conv_w rearranged [dout][ktap*1024+din]
__device__ float g_comp[256 * DIM];          // conv split-K accumulator (fp32)

// ---------------- helpers ----------------
__device__ __forceinline__ uint32_t pack2(float a, float b) {
    __half2 h = __floats2half2_rn(a, b);
    return *(uint32_t*)&h;
}
__device__ __forceinline__ uint32_t smem_u32(const void* p) {
    uint32_t a;
    asm("{ .reg .u64 t; cvta.to.shared.u64 t, %1; cvt.u32.u64 %0, t; }"
        : "=r"(a) : "l"(p));
    return a;
}
__device__ __forceinline__ void cp_async16(uint32_t dst, const void* src) {
    asm volatile("cp.async.cg.shared.global [%0], [%1], 16;"
                 :: "r"(dst), "l"(__cvta_generic_to_global(src)) : "memory");
}
__device__ __forceinline__ void cp_commit() {
    asm volatile("cp.async.commit_group;" ::: "memory");
}

__device__ __forceinline__ void ldsm_x4(uint32_t& r0, uint32_t& r1, uint32_t& r2,
                                        uint32_t& r3, uint32_t addr) {
    asm volatile("ldmatrix.sync.aligned.m8n8.x4.shared.b16 {%0,%1,%2,%3}, [%4];"
                 : "=r"(r0), "=r"(r1), "=r"(r2), "=r"(r3) : "r"(addr));
}
__device__ __forceinline__ void ldsm_x4_t(uint32_t& r0, uint32_t& r1, uint32_t& r2,
                                          uint32_t& r3, uint32_t addr) {
    asm volatile("ldmatrix.sync.aligned.m8n8.x4.trans.shared.b16 {%0,%1,%2,%3}, [%4];"
                 : "=r"(r0), "=r"(r1), "=r"(r2), "=r"(r3) : "r"(addr));
}

// fast exp on fma/alu pipes (no MUFU). |rel err| ~2e-6 for x <= 0.
__device__ __forceinline__ float fexp(float x) {
    float z = fmaxf(x, -87.3365f) * 1.4426950408889634f;
    float s = z + 12582912.0f;
    int n = __float_as_int(s) - 0x4b400000;
    float f = z - (s - 12582912.0f);
    float p = 1.3371542e-3f;
    p = fmaf(p, f, 9.6181291e-3f);
    p = fmaf(p, f, 5.5504109e-2f);
    p = fmaf(p, f, 2.4022651e-1f);
    p = fmaf(p, f, 6.9314718e-1f);
    p = fmaf(p, f, 1.0f);
    return __int_as_float(__float_as_int(p) + (n << 23));
}

// fp16 mma with fp32 accum: D = A(16x16) B(16x8) + D
__device__ __forceinline__ void mma_f16(float* c, uint32_t a0, uint32_t a1,
                                        uint32_t a2, uint32_t a3,
                                        uint32_t b0, uint32_t b1) {
    asm volatile(
        "mma.sync.aligned.m16n8k16.row.col.f32.f16.f16.f32 "
        "{%0,%1,%2,%3}, {%4,%5,%6,%7}, {%8,%9}, {%0,%1,%2,%3};"
        : "+f"(c[0]), "+f"(c[1]), "+f"(c[2]), "+f"(c[3])
        : "r"(a0), "r"(a1), "r"(a2), "r"(a3), "r"(b0), "r"(b1));
}

#define LDH32(arr, idx) (*(const uint32_t*)((arr) + (idx)))

// ---------------- kernel: x + pos_emb -> fp16 ----------------
__global__ __launch_bounds__(256) void add_pos_kernel(const float* __restrict__ x,
                                                      const float* __restrict__ pe) {
    int i = blockIdx.x * 256 + threadIdx.x;
    float4 a = ((const float4*)x)[i];
    float4 p = ((const float4*)pe)[i & 1048575];
    ((uint2*)g_xph)[i] = make_uint2(pack2(a.x + p.x, a.y + p.y),
                                    pack2(a.z + p.z, a.w + p.w));
}

// ---------------- fill global_memory half of gt (fp16) ----------------
__global__ __launch_bounds__(256) void gt_fill_kernel(const float* __restrict__ gm) {
    int i = blockIdx.x * 256 + threadIdx.x;
    float4 v = ((const float4*)gm)[i & 16383];
    *(uint2*)(g_gth + (i >> 14) * 131072 + 65536 + (i & 16383) * 4) =
        make_uint2(pack2(v.x, v.y), pack2(v.z, v.w));
}

// ---------------- transpose + fp16: in[K][N] -> out[N][K] ----------------
__global__ __launch_bounds__(256) void transpose_kernel(const float* __restrict__ in,
                                                        __half* __restrict__ out,
                                                        int K, int N) {
    __shared__ float t[32][33];
    int bx = blockIdx.x * 32;
    int by = blockIdx.y * 32;
    int x = threadIdx.x & 31, y = threadIdx.x >> 5;
#pragma unroll
    for (int i = 0; i < 32; i += 8) t[y + i][x] = in[(by + y + i) * N + bx + x];
    __syncthreads();
#pragma unroll
    for (int i = 0; i < 32; i += 8)
        out[(bx + y + i) * K + by + x] = __float2half_rn(t[x][y + i]);
}

// ---------------- conv pre-transforms ----------------
__global__ __launch_bounds__(256) void cw_rearrange_kernel(const float* __restrict__ cw) {
    int i = blockIdx.x * 256 + threadIdx.x;
    int dout = i >> 10, q = i & 1023;
    int c4 = q << 2;
    int ktap = c4 >> 10, din = c4 & 1023;
    const float* base = cw + dout * 4096 + din * 4 + ktap;
    *(uint2*)(g_cwT + dout * 4096 + c4) =
        make_uint2(pack2(base[0], base[4]), pack2(base[8], base[12]));
}

__global__ __launch_bounds__(256) void zero_comp_kernel() {
    int i = blockIdx.x * 256 + threadIdx.x;
    ((float4*)g_comp)[i] = make_float4(0.f, 0.f, 0.f, 0.f);
}

// comp + bias -> gth rows (b*128 + g), fp16
__global__ __launch_bounds__(256) void conv_scatter_kernel(const float* __restrict__ cb) {
    int i = blockIdx.x * 256 + threadIdx.x;
    int r = i >> 8, c4 = (i & 255) << 2;
    float4 v = *(const float4*)(g_comp + r * 1024 + c4);
    float4 b = *(const float4*)(cb + c4);
    int outr = ((r >> 6) << 7) | (r & 63);
    *(uint2*)(g_gth + outr * 1024 + c4) =
        make_uint2(pack2(v.x + b.x, v.y + b.y), pack2(v.z + b.z, v.w + b.w));
}

// ===== fp16 flash attention, ldmatrix + register P + cp.async K pipeline =====
// smem: 2 x Ks[64][72] halves = 18432 bytes (also reused once for Q staging).
__device__ __forceinline__ void flash_mma(const __half* __restrict__ qb,
                                          const __half* __restrict__ kb,
                                          __half* __restrict__ obp, int nkt) {
    extern __shared__ __half smh[];
    const uint32_t smbase = smem_u32(smh);
    const int tid = threadIdx.x;
    const int warp = tid >> 5, lane = tid & 31;
    const int g = lane >> 2, tg = lane & 3;
    const int wm = warp * 16;

    // ---- stage Q (scaled 1/8) into both buffers (128 rows x 72) ----
    const __half2 sc2 = __float2half2_rn(0.125f);
#pragma unroll
    for (int it = 0; it < 4; ++it) {
        int f = tid + it * 256;            // 1024 slots: 128 rows x 8
        int row = f >> 3, c8 = (f & 7) << 3;
        uint4 v = *(const uint4*)(qb + row * DIM + c8);
        __half2* hv = (__half2*)&v;
#pragma unroll
        for (int j = 0; j < 4; ++j) hv[j] = __hmul2(hv[j], sc2);
        *(uint4*)(smh + row * 72 + c8) = v;
    }
    __syncthreads();

    // ---- Q fragments via ldmatrix x4 (one per 16-wide k-step) ----
    uint32_t qf[4][4];
#pragma unroll
    for (int ks = 0; ks < 4; ++ks) {
        int row = wm + (lane & 7) + ((lane >> 3) & 1) * 8;
        int col = ks * 16 + (lane >> 4) * 8;
        ldsm_x4(qf[ks][0], qf[ks][1], qf[ks][2], qf[ks][3],
                smbase + (row * 72 + col) * 2);
    }
    __syncthreads();  // Q frag reads done before K prefetch overwrites

    // ---- prefetch K tile 0 into buf 0 ----
#pragma unroll
    for (int it = 0; it < 2; ++it) {
        int f = tid + it * 256;            // 512 slots: 64 rows x 8
        int row = f >> 3, c8 = (f & 7) << 3;
        cp_async16(smbase + (row * 72 + c8) * 2, kb + row * DIM + c8);
    }
    cp_commit();

    float m0 = -1e30f, m1 = -1e30f, l0 = 0.f, l1 = 0.f;
    float oacc[8][4];
#pragma unroll
    for (int j = 0; j < 8; ++j)
#pragma unroll
        for (int q = 0; q < 4; ++q) oacc[j][q] = 0.f;

    for (int kt = 0; kt < nkt; ++kt) {
        asm volatile("cp.async.wait_group 0;" ::: "memory");
        __syncthreads();  // buf[kt&1] ready; prior reads of buf[(kt+1)&1] done
        const uint32_t cur = smbase + (kt & 1) * 9216;   // 4608 halves * 2B

        // prefetch next tile (overlaps with compute below)
        if (kt + 1 < nkt) {
            const uint32_t nxt = smbase + ((kt + 1) & 1) * 9216;
            const __half* kbn = kb + (kt + 1) * 64 * DIM;
#pragma unroll
            for (int it = 0; it < 2; ++it) {
                int f = tid + it * 256;
                int row = f >> 3, c8 = (f & 7) << 3;
                cp_async16(nxt + (row * 72 + c8) * 2, kbn + row * DIM + c8);
            }
            cp_commit();
        }

        // ---- S = Q K^T (B-frags via non-trans ldmatrix on K rows) ----
        float sacc[8][4];
#pragma unroll
        for (int j = 0; j < 8; ++j)
#pragma unroll
            for (int q = 0; q < 4; ++q) sacc[j][q] = 0.f;
#pragma unroll
        for (int j = 0; j < 8; ++j) {
#pragma unroll
            for (int kp = 0; kp < 2; ++kp) {
                int row = j * 8 + (lane & 7);
                int col = kp * 32 + (lane >> 3) * 8;
                uint32_t b0, b1, b2, b3;
                ldsm_x4(b0, b1, b2, b3, cur + (row * 72 + col) * 2);
                mma_f16(sacc[j], qf[2 * kp][0], qf[2 * kp][1], qf[2 * kp][2],
                        qf[2 * kp][3], b0, b1);
                mma_f16(sacc[j], qf[2 * kp + 1][0], qf[2 * kp + 1][1],
                        qf[2 * kp + 1][2], qf[2 * kp + 1][3], b2, b3);
            }
        }

        // ---- online softmax (quad-local reductions) ----
        float mx0 = -1e30f, mx1 = -1e30f;
#pragma unroll
        for (int j = 0; j < 8; ++j) {
            mx0 = fmaxf(mx0, fmaxf(sacc[j][0], sacc[j][1]));
            mx1 = fmaxf(mx1, fmaxf(sacc[j][2], sacc[j][3]));
        }
        mx0 = fmaxf(mx0, __shfl_xor_sync(0xffffffffu, mx0, 1));
        mx0 = fmaxf(mx0, __shfl_xor_sync(0xffffffffu, mx0, 2));
        mx1 = fmaxf(mx1, __shfl_xor_sync(0xffffffffu, mx1, 1));
        mx1 = fmaxf(mx1, __shfl_xor_sync(0xffffffffu, mx1, 2));
        float mn0 = fmaxf(m0, mx0), mn1 = fmaxf(m1, mx1);
        float c0 = fexp(m0 - mn0), c1 = fexp(m1 - mn1);
        m0 = mn0; m1 = mn1;
        float s0 = 0.f, s1 = 0.f;
#pragma unroll
        for (int j = 0; j < 8; ++j) {
            sacc[j][0] = fexp(sacc[j][0] - mn0);
            sacc[j][1] = fexp(sacc[j][1] - mn0);
            sacc[j][2] = fexp(sacc[j][2] - mn1);
            sacc[j][3] = fexp(sacc[j][3] - mn1);
            s0 += sacc[j][0] + sacc[j][1];
            s1 += sacc[j][2] + sacc[j][3];
        }
        s0 += __shfl_xor_sync(0xffffffffu, s0, 1);
        s0 += __shfl_xor_sync(0xffffffffu, s0, 2);
        s1 += __shfl_xor_sync(0xffffffffu, s1, 1);
        s1 += __shfl_xor_sync(0xffffffffu, s1, 2);
        l0 = l0 * c0 + s0;
        l1 = l1 * c1 + s1;
#pragma unroll
        for (int j = 0; j < 8; ++j) {
            oacc[j][0] *= c0; oacc[j][1] *= c0;
            oacc[j][2] *= c1; oacc[j][3] *= c1;
        }

        // ---- O += P V: P A-frags straight from sacc registers (fp16 pack),
        //      V B-frags via trans ldmatrix on the row-major K tile ----
#pragma unroll
        for (int ks = 0; ks < 4; ++ks) {
            uint32_t pa0 = pack2(sacc[2 * ks][0], sacc[2 * ks][1]);
            uint32_t pa1 = pack2(sacc[2 * ks][2], sacc[2 * ks][3]);
            uint32_t pa2 = pack2(sacc[2 * ks + 1][0], sacc[2 * ks + 1][1]);
            uint32_t pa3 = pack2(sacc[2 * ks + 1][2], sacc[2 * ks + 1][3]);
#pragma unroll
            for (int j2 = 0; j2 < 4; ++j2) {
                int row = ks * 16 + (lane & 15);
                int col = j2 * 16 + (lane >> 4) * 8;
                uint32_t b0, b1, b2, b3;
                ldsm_x4_t(b0, b1, b2, b3, cur + (row * 72 + col) * 2);
                mma_f16(oacc[2 * j2], pa0, pa1, pa2, pa3, b0, b1);
                mma_f16(oacc[2 * j2 + 1], pa0, pa1, pa2, pa3, b2, b3);
            }
        }
    }

    // normalize + store fp16
    float inv0 = 1.0f / l0, inv1 = 1.0f / l1;
#pragma unroll
    for (int j = 0; j < 8; ++j) {
        int cb = j * 8 + 2 * tg;
        *(uint32_t*)(obp + (wm + g) * DIM + cb) =
            pack2(oacc[j][0] * inv0, oacc[j][1] * inv0);
        *(uint32_t*)(obp + (wm + g + 8) * DIM + cb) =
            pack2(oacc[j][2] * inv1, oacc[j][3] * inv1);
    }
}

// merged attention: blocks [0,2048) local, [2048,4096) global
__global__ __launch_bounds__(256, 2) void attn_kernel() {
    int bx = blockIdx.x;
    if (bx < 2048) {
        int qt = bx & 3;
        int h = (bx >> 2) & 15;
        int w = (bx >> 6) & 7;
        int b = bx >> 9;
        const __half* base = g_xph + (b * SEQ + w * WINS) * DIM + h * HDIM;
        const __half* qb = base + (qt * 128) * DIM;
        __half* ob = g_local + (b * SEQ + w * WINS + qt * 128) * DIM + h * HDIM;
        flash_mma(qb, base, ob, 8);
    } else {
        bx -= 2048;
        int qt = bx & 31;
        int h = (bx >> 5) & 15;
        int b = bx >> 9;
        const __half* qb = g_xph + (b * SEQ + qt * 128) * DIM + h * HDIM;
        const __half* kb = g_gth + b * NGT * DIM + h * HDIM;
        __half* ob = g_glob + (b * SEQ + qt * 128) * DIM + h * HDIM;
        flash_mma(qb, kb, ob, 2);
    }
}

// ============== pipelined fp16 mma GEMM, 128x128 tile, KT=32 halves ==============
#define STG_H 10240
#define GP_SMEM (2 * STG_H * 2)

template <int MODE>
__device__ __forceinline__ void gp_load(__half* sm, int s, int m0, int n0, int k0,
                                        const __half* Bsrc, int tid) {
    __half* A = sm + s * STG_H;
    __half* B = A + 5120;
    constexpr int KTOT = (MODE == 0) ? 4096 : (MODE == 1) ? 2048 : 1024;
#pragma unroll
    for (int t = 0; t < 2; ++t) {
        int id = tid + t * 256;
        int r = id >> 2, q = id & 3;
        int kk = k0 + q * 8;
        const __half* src;
        if (MODE == 0) {
            int row = m0 + r;  // conv A row = reshape of xph
            src = g_xph + ((row >> 6) * SEQ + (row & 63) * 4) * DIM + kk;
        } else if (MODE == 1) {
            src = (kk < 1024) ? g_local + (m0 + r) * 1024 + kk
                              : g_glob + (m0 + r) * 1024 + (kk - 1024);
        } else {
            src = g_mixed + (m0 + r) * 1024 + kk;
        }
        cp_async16(smem_u32(A + r * 40 + q * 8), src);
    }
#pragma unroll
    for (int t = 0; t < 2; ++t) {
        int id = tid + t * 256;
        int r = id >> 2, q = id & 3;
        cp_async16(smem_u32(B + r * 40 + q * 8), Bsrc + (n0 + r) * KTOT + k0 + q * 8);
    }
    cp_commit();
}

template <int MODE>
__global__ __launch_bounds__(256) void gemm_pipe(const float* __restrict__ bias,
                                                 float* __restrict__ Cext) {
    constexpr int NIT = (MODE == 0) ? 16 : (MODE == 1) ? 64 : 32;
    extern __shared__ __half smh[];
    const int tid = threadIdx.x;
    const int warp = tid >> 5, lane = tid & 31;
    const int g = lane >> 2, tg = lane & 3;
    const int wm = (warp >> 1) * 32, wn = (warp & 1) * 64;
    const int m0 = blockIdx.y * 128, n0 = blockIdx.x * 128;
    const int kbase = (MODE == 0) ? blockIdx.z * 512 : 0;
    const __half* Bsrc = (MODE == 0) ? g_cwT : (MODE == 1) ? g_gwT : g_owT;

    float acc[2][8][4];
#pragma unroll
    for (int mt = 0; mt < 2; ++mt)
#pragma unroll
        for (int j = 0; j < 8; ++j)
#pragma unroll
            for (int q = 0; q < 4; ++q) acc[mt][j][q] = 0.f;

    gp_load<MODE>(smh, 0, m0, n0, kbase, Bsrc, tid);

    for (int i = 0; i < NIT; ++i) {
        if (i + 1 < NIT) {
            gp_load<MODE>(smh, (i + 1) & 1, m0, n0, kbase + (i + 1) * 32, Bsrc, tid);
            asm volatile("cp.async.wait_group 1;" ::: "memory");
        } else {
            asm volatile("cp.async.wait_group 0;" ::: "memory");
        }
        __syncthreads();

        const __half* As = smh + (i & 1) * STG_H;
        const __half* Bs = As + 5120;
#pragma unroll
        for (int ks = 0; ks < 2; ++ks) {
            uint32_t bf[8][2];
#pragma unroll
            for (int j = 0; j < 8; ++j) {
                int n = wn + j * 8 + g;
                bf[j][0] = LDH32(Bs, n * 40 + ks * 16 + 2 * tg);
                bf[j][1] = LDH32(Bs, n * 40 + ks * 16 + 2 * tg + 8);
            }
#pragma unroll
            for (int mt = 0; mt < 2; ++mt) {
                int r0 = wm + mt * 16 + g;
                uint32_t a0 = LDH32(As, r0 * 40 + ks * 16 + 2 * tg);
                uint32_t a1 = LDH32(As, (r0 + 8) * 40 + ks * 16 + 2 * tg);
                uint32_t a2 = LDH32(As, r0 * 40 + ks * 16 + 2 * tg + 8);
                uint32_t a3 = LDH32(As, (r0 + 8) * 40 + ks * 16 + 2 * tg + 8);
#pragma unroll
                for (int j = 0; j < 8; ++j)
                    mma_f16(acc[mt][j], a0, a1, a2, a3, bf[j][0], bf[j][1]);
            }
        }
        __syncthreads();
    }

    // ---- epilogue ----
#pragma unroll
    for (int mt = 0; mt < 2; ++mt) {
#pragma unroll
        for (int j = 0; j < 8; ++j) {
            int col = n0 + wn + j * 8 + 2 * tg;
            int ra = m0 + wm + mt * 16 + g;
            int rb = ra + 8;
            if (MODE == 0) {
                atomicAdd(&g_comp[ra * 1024 + col], acc[mt][j][0]);
                atomicAdd(&g_comp[ra * 1024 + col + 1], acc[mt][j][1]);
                atomicAdd(&g_comp[rb * 1024 + col], acc[mt][j][2]);
                atomicAdd(&g_comp[rb * 1024 + col + 1], acc[mt][j][3]);
                continue;
            }
            float2 bz = *(const float2*)&bias[col];
            float z0x = acc[mt][j][0] + bz.x, z0y = acc[mt][j][1] + bz.y;
            float z1x = acc[mt][j][2] + bz.x, z1y = acc[mt][j][3] + bz.y;
            if (MODE == 1) {
                int ia = ra * 1024 + col, ib = rb * 1024 + col;
                float2 la = __half22float2(*(const __half2*)(g_local + ia));
                float2 lb = __half22float2(*(const __half2*)(g_local + ib));
                float2 ga = __half22float2(*(const __half2*)(g_glob + ia));
                float2 gb = __half22float2(*(const __half2*)(g_glob + ib));
                float s0x = 1.0f / (1.0f + fexp(-z0x));
                float s0y = 1.0f / (1.0f + fexp(-z0y));
                float s1x = 1.0f / (1.0f + fexp(-z1x));
                float s1y = 1.0f / (1.0f + fexp(-z1y));
                *(uint32_t*)(g_mixed + ia) =
                    pack2(s0x * la.x + (1.f - s0x) * ga.x,
                          s0y * la.y + (1.f - s0y) * ga.y);
                *(uint32_t*)(g_mixed + ib) =
                    pack2(s1x * lb.x + (1.f - s1x) * gb.x,
                          s1y * lb.y + (1.f - s1y) * gb.y);
            } else {
                *(float2*)&Cext[ra * 1024 + col] = make_float2(z0x, z0y);
                *(float2*)&Cext[rb * 1024 + col] = make_float2(z1x, z1y);
            }
        }
    }
}

// ---------------- launch ----------------
extern "C" void kernel_launch(void* const* d_in, const int* in_sizes, int n_in,
                              void* d_out, int out_size) {
    const float* x = (const float*)d_in[0];
    const float* pe = (const float*)d_in[1];
    const float* gm = (const float*)d_in[2];
    const float* cw = (const float*)d_in[3];
    const float* cb = (const float*)d_in[4];
    const float* gw = (const float*)d_in[5];
    const float* gb = (const float*)d_in[6];
    const float* ow = (const float*)d_in[7];
    const float* ob = (const float*)d_in[8];
    float* out = (float*)d_out;

    cudaFuncSetAttribute((const void*)attn_kernel,
                         cudaFuncAttributeMaxDynamicSharedMemorySize, 18432);
    cudaFuncSetAttribute((const void*)gemm_pipe<0>,
                         cudaFuncAttributeMaxDynamicSharedMemorySize, GP_SMEM);
    cudaFuncSetAttribute((const void*)gemm_pipe<1>,
                         cudaFuncAttributeMaxDynamicSharedMemorySize, GP_SMEM);
    cudaFuncSetAttribute((const void*)gemm_pipe<2>,
                         cudaFuncAttributeMaxDynamicSharedMemorySize, GP_SMEM);

    add_pos_kernel<<<16384, 256>>>(x, pe);
    {
        __half* gwT; __half* owT;
        cudaGetSymbolAddress((void**)&gwT, g_gwT);
        cudaGetSymbolAddress((void**)&owT, g_owT);
        transpose_kernel<<<dim3(32, 64), 256>>>(gw, gwT, 2048, 1024);
        transpose_kernel<<<dim3(32, 32), 256>>>(ow, owT, 1024, 1024);
    }
    cw_rearrange_kernel<<<4096, 256>>>(cw);
    zero_comp_kernel<<<256, 256>>>();
    gemm_pipe<0><<<dim3(8, 2, 8), 256, GP_SMEM>>>(nullptr, nullptr);  // conv split-K
    conv_scatter_kernel<<<256, 256>>>(cb);
    gt_fill_kernel<<<256, 256>>>(gm);
    attn_kernel<<<4096, 256, 18432>>>();
    gemm_pipe<1><<<dim3(8, 128), 256, GP_SMEM>>>(gb, nullptr);  // gate + mix
    gemm_pipe<2><<<dim3(8, 128), 256, GP_SMEM>>>(ob, out);      // output projection
}